// round 6
// baseline (speedup 1.0000x reference)
#include <cuda_runtime.h>

// Problem constants
#define Bn     16
#define Rn     128
#define Tn     128
#define Hn     32
#define En     64
#define IN0    65     // E+1
#define VOCABn 258
#define NTOK   (Bn*Rn*Tn)   // 262144

// Scratch: top-layer GRU outputs [token][H], and per-(row,batch) progress flags.
__device__ float g_out_h[(size_t)NTOK * Hn];      // 33.5M floats
__device__ int   g_progress[Rn * Bn];

// ---------------------------------------------------------------------------

__device__ __forceinline__ int ld_acq(const int* p) {
    int v;
    asm volatile("ld.global.acquire.gpu.b32 %0, [%1];" : "=r"(v) : "l"(p) : "memory");
    return v;
}

__device__ __forceinline__ float sigm(float x) {
    return __fdividef(1.0f, 1.0f + __expf(-x));
}
__device__ __forceinline__ float tanh_f(float x) {
    float e = __expf(2.0f * x);            // e -> inf or 0 at extremes, both safe
    return 1.0f - __fdividef(2.0f, e + 1.0f);
}

// 32-step broadcast dot: src is lane-distributed (lane i holds element i).
// Weight layout: w[i*32 + j] = {W_r[j][i], W_z[j][i], W_n[j][i], pad}
__device__ __forceinline__ void dot32(const float4* __restrict__ w, int j, float src,
                                      float& a, float& b, float& c) {
#pragma unroll
    for (int i = 0; i < 32; ++i) {
        float v = __shfl_sync(0xffffffffu, src, i);
        float4 ww = w[i * 32 + j];
        a = fmaf(ww.x, v, a);
        b = fmaf(ww.y, v, b);
        c = fmaf(ww.z, v, c);
    }
}

// ---------------------------------------------------------------------------

__global__ void init_kernel() {
    int i = blockIdx.x * blockDim.x + threadIdx.x;
    if (i < Rn * Bn) g_progress[i] = 0;
}

// ---------------------------------------------------------------------------
// RNN wavefront kernel: blockIdx.x = row r; warp w = batch b; lane j = hidden idx.
// Shared memory layout (floats):
//   s_wih0 : 65*128   (layer0 input weights, padded float4 per (i,j))
//   s_whh0 : 32*128
//   s_wih1 : 32*128
//   s_whh1 : 32*128
//   s_wih2 : 32*128
//   s_whh2 : 32*128
//   s_wh2e : 32*128   ({W[j][h], W[32+j][h], W[64][h], pad})
#define SM_WIH0  0
#define SM_WHH0  (65*128)
#define SM_WIH1  (SM_WHH0 + 32*128)
#define SM_WHH1  (SM_WIH1 + 32*128)
#define SM_WIH2  (SM_WHH1 + 32*128)
#define SM_WHH2  (SM_WIH2 + 32*128)
#define SM_WH2E  (SM_WHH2 + 32*128)
#define SM_TOTAL (SM_WH2E + 32*128)
#define SMEM_BYTES (SM_TOTAL * 4)

extern __shared__ float s_rnn[];

__global__ __launch_bounds__(512, 1) void rnn_kernel(
    const int*   __restrict__ x,
    const float* __restrict__ emb,
    const float* __restrict__ wih0, const float* __restrict__ whh0,
    const float* __restrict__ bih0, const float* __restrict__ bhh0,
    const float* __restrict__ wih1, const float* __restrict__ whh1,
    const float* __restrict__ bih1, const float* __restrict__ bhh1,
    const float* __restrict__ wih2, const float* __restrict__ whh2,
    const float* __restrict__ bih2, const float* __restrict__ bhh2,
    const float* __restrict__ wh2e, const float* __restrict__ bh2e)
{
    const int r   = blockIdx.x;
    const int tid = threadIdx.x;

    // ---- stage weights into smem (transposed, float4-padded) ----
    // wih0: [96][65] -> s[i*128 + (g&31)*4 + (g>>5)]
    for (int n = tid; n < 96 * 65; n += 512) {
        int g = n / 65, i = n - g * 65;
        s_rnn[SM_WIH0 + i * 128 + ((g & 31) << 2) + (g >> 5)] = wih0[n];
    }
    {
        const float* srcs[5] = { whh0, wih1, whh1, wih2, whh2 };
        const int    offs[5] = { SM_WHH0, SM_WIH1, SM_WHH1, SM_WIH2, SM_WHH2 };
#pragma unroll
        for (int m = 0; m < 5; ++m) {
            const float* s = srcs[m];
            float* d = s_rnn + offs[m];
            for (int n = tid; n < 96 * 32; n += 512) {
                int g = n >> 5, i = n & 31;
                d[i * 128 + ((g & 31) << 2) + (g >> 5)] = s[n];
            }
        }
    }
    // wh2e: [65][32]; e<64 -> slots 0/1; e==64 broadcast into slot 2 for all j
    for (int n = tid; n < 64 * 32; n += 512) {
        int e = n >> 5, h = n & 31;
        s_rnn[SM_WH2E + h * 128 + ((e & 31) << 2) + (e >> 5)] = wh2e[n];
    }
    for (int n = tid; n < 32 * 32; n += 512) {
        int h = n & 31, j = n >> 5;
        s_rnn[SM_WH2E + h * 128 + (j << 2) + 2] = wh2e[64 * 32 + h];
    }
    __syncthreads();

    const int b = tid >> 5;
    const int j = tid & 31;

    const float4* w4_ih0 = (const float4*)(s_rnn + SM_WIH0);
    const float4* w4_hh0 = (const float4*)(s_rnn + SM_WHH0);
    const float4* w4_ih1 = (const float4*)(s_rnn + SM_WIH1);
    const float4* w4_hh1 = (const float4*)(s_rnn + SM_WHH1);
    const float4* w4_ih2 = (const float4*)(s_rnn + SM_WIH2);
    const float4* w4_hh2 = (const float4*)(s_rnn + SM_WHH2);
    const float4* w4_h2e = (const float4*)(s_rnn + SM_WH2E);

    // per-lane biases
    const float bi0r = bih0[j], bi0z = bih0[32 + j], bi0n = bih0[64 + j];
    const float bh0r = bhh0[j], bh0z = bhh0[32 + j], bh0n = bhh0[64 + j];
    const float bi1r = bih1[j], bi1z = bih1[32 + j], bi1n = bih1[64 + j];
    const float bh1r = bhh1[j], bh1z = bhh1[32 + j], bh1n = bhh1[64 + j];
    const float bi2r = bih2[j], bi2z = bih2[32 + j], bi2n = bih2[64 + j];
    const float bh2r = bhh2[j], bh2z = bhh2[32 + j], bh2n = bhh2[64 + j];
    const float be0 = bh2e[j], be1 = bh2e[32 + j], be2 = bh2e[64];

    const float rf = (float)r * (2.0f / 128.0f) - 1.0f;

    const int xbase = (b * Rn + r) * Tn;
    const size_t obase = (size_t)(b * Rn + r) * Tn * Hn + j;
    const size_t pbase = (r > 0) ? ((size_t)(b * Rn + (r - 1)) * Tn * Hn + j) : 0;
    int* myflag = &g_progress[r * Bn + b];
    const int* waitflag = (r > 0) ? &g_progress[(r - 1) * Bn + b] : (const int*)0;

    float h0 = 0.0f, h1 = 0.0f, h2 = 0.0f;

    for (int t = 0; t < Tn; ++t) {
        // ---- comb = emb|rowfeat + prev_out @ W_h2e^T + b_h2e ----
        float c0, c1, c2;
        {
            int xv = x[xbase + t];
            c0 = emb[xv * En + j]       + be0;
            c1 = emb[xv * En + 32 + j]  + be1;
            c2 = rf + be2;
        }
        if (r > 0) {
            // all lanes spin on the same flag (broadcast load, converged)
            while (ld_acq(waitflag) <= t) { }
            float pv = __ldcg(&g_out_h[pbase + (size_t)t * Hn]);
            dot32(w4_h2e, j, pv, c0, c1, c2);
        }

        // ---- layer 0 (input dim 65) ----
        float gr = bi0r + bh0r, gz = bi0z + bh0z, gni = bi0n, gnh = bh0n;
        dot32(w4_ih0, j, c0, gr, gz, gni);
        dot32(w4_ih0 + 32 * 32, j, c1, gr, gz, gni);
        {
            float4 ww = w4_ih0[64 * 32 + j];   // input 64 (row feature), uniform value c2
            gr  = fmaf(ww.x, c2, gr);
            gz  = fmaf(ww.y, c2, gz);
            gni = fmaf(ww.z, c2, gni);
        }
        dot32(w4_hh0, j, h0, gr, gz, gnh);
        {
            float rr = sigm(gr), zz = sigm(gz);
            float nn = tanh_f(fmaf(rr, gnh, gni));
            h0 = fmaf(zz, h0 - nn, nn);
        }

        // ---- layer 1 ----
        gr = bi1r + bh1r; gz = bi1z + bh1z; gni = bi1n; gnh = bh1n;
        dot32(w4_ih1, j, h0, gr, gz, gni);
        dot32(w4_hh1, j, h1, gr, gz, gnh);
        {
            float rr = sigm(gr), zz = sigm(gz);
            float nn = tanh_f(fmaf(rr, gnh, gni));
            h1 = fmaf(zz, h1 - nn, nn);
        }

        // ---- layer 2 ----
        gr = bi2r + bh2r; gz = bi2z + bh2z; gni = bi2n; gnh = bh2n;
        dot32(w4_ih2, j, h1, gr, gz, gni);
        dot32(w4_hh2, j, h2, gr, gz, gnh);
        {
            float rr = sigm(gr), zz = sigm(gz);
            float nn = tanh_f(fmaf(rr, gnh, gni));
            h2 = fmaf(zz, h2 - nn, nn);
        }

        // ---- publish ----
        __stcg(&g_out_h[obase + (size_t)t * Hn], h2);
        __syncwarp();
        if (j == 0) {
            __threadfence();
            asm volatile("st.global.release.gpu.b32 [%0], %1;" :: "l"(myflag), "r"(t + 1) : "memory");
        }
    }
}

// ---------------------------------------------------------------------------
// Output projection: pred[n][v] = sum_h out_h[n][h] * w_out[v][h] + b_out[v]
// 64 tokens per block, v computed as f32x2 pairs (129 pairs cover 258).
#define PROJ_TOK 64

__global__ __launch_bounds__(256) void proj_kernel(
    const float* __restrict__ w_out,
    const float* __restrict__ b_out,
    float* __restrict__ pred)
{
    __shared__ float w_s[32 * 260];     // [h][v] padded to 260 (float2-friendly)
    __shared__ float h_s[PROJ_TOK * 32];
    __shared__ float b_s[260];

    const int tid = threadIdx.x;

    for (int n = tid; n < VOCABn * 32; n += 256) {
        int v = n >> 5, h = n & 31;
        w_s[h * 260 + v] = w_out[n];
    }
    for (int n = tid; n < VOCABn; n += 256) b_s[n] = b_out[n];
    if (tid < 2) b_s[VOCABn + tid] = 0.0f;

    const size_t tok0 = (size_t)blockIdx.x * PROJ_TOK;
    const float* src = g_out_h + tok0 * 32;
    for (int n = tid; n < PROJ_TOK * 32; n += 256) h_s[n] = src[n];
    __syncthreads();

    for (int idx = tid; idx < PROJ_TOK * 129; idx += 256) {
        int tok = idx / 129;
        int p   = idx - tok * 129;        // v = 2p, 2p+1 ; p in [0,128]
        unsigned long long acc = *(const unsigned long long*)&b_s[2 * p];
        const float* hs = &h_s[tok * 32];
        const unsigned long long* wp = (const unsigned long long*)&w_s[2 * p];
#pragma unroll
        for (int h = 0; h < 32; ++h) {
            float hv = hs[h];
            unsigned long long w2 = wp[(size_t)h * 130];
            unsigned long long h2;
            asm("mov.b64 %0, {%1, %1};" : "=l"(h2) : "f"(hv));
            asm("fma.rn.f32x2 %0, %1, %2, %3;" : "=l"(acc) : "l"(w2), "l"(h2), "l"(acc));
        }
        *(unsigned long long*)&pred[(tok0 + (size_t)tok) * VOCABn + 2 * p] = acc;
    }
}

// ---------------------------------------------------------------------------

extern "C" void kernel_launch(void* const* d_in, const int* in_sizes, int n_in,
                              void* d_out, int out_size)
{
    const int*   x     = (const int*)  d_in[0];
    const float* emb   = (const float*)d_in[1];
    const float* wih0  = (const float*)d_in[2];
    const float* whh0  = (const float*)d_in[3];
    const float* bih0  = (const float*)d_in[4];
    const float* bhh0  = (const float*)d_in[5];
    const float* wih1  = (const float*)d_in[6];
    const float* whh1  = (const float*)d_in[7];
    const float* bih1  = (const float*)d_in[8];
    const float* bhh1  = (const float*)d_in[9];
    const float* wih2  = (const float*)d_in[10];
    const float* whh2  = (const float*)d_in[11];
    const float* bih2  = (const float*)d_in[12];
    const float* bhh2  = (const float*)d_in[13];
    const float* wh2e  = (const float*)d_in[14];
    const float* bh2e  = (const float*)d_in[15];
    const float* w_out = (const float*)d_in[16];
    const float* b_out = (const float*)d_in[17];
    float* pred = (float*)d_out;

    cudaFuncSetAttribute(rnn_kernel, cudaFuncAttributeMaxDynamicSharedMemorySize, SMEM_BYTES);

    init_kernel<<<4, 512>>>();
    rnn_kernel<<<Rn, 512, SMEM_BYTES>>>(x, emb,
        wih0, whh0, bih0, bhh0,
        wih1, whh1, bih1, bhh1,
        wih2, whh2, bih2, bhh2,
        wh2e, bh2e);
    proj_kernel<<<NTOK / PROJ_TOK, 256>>>(w_out, b_out, pred);
}

// round 7
// speedup vs baseline: 1.1226x; 1.1226x over previous
#include <cuda_runtime.h>

// Problem constants
#define Bn     16
#define Rn     128
#define Tn     128
#define Hn     32
#define En     64
#define VOCABn 258
#define NTOK   (Bn*Rn*Tn)   // 262144

// Scratch: top-layer GRU outputs [b][r][t][h], and per-(row,group) progress flags.
__device__ float g_out_h[(size_t)NTOK * Hn];
__device__ int   g_progress[Rn * 4];

// ---------------------------------------------------------------------------

__device__ __forceinline__ int ld_acq(const int* p) {
    int v;
    asm volatile("ld.global.acquire.gpu.b32 %0, [%1];" : "=r"(v) : "l"(p) : "memory");
    return v;
}
__device__ __forceinline__ float sigm(float x) {
    return __fdividef(1.0f, 1.0f + __expf(-x));
}
__device__ __forceinline__ float tanh_f(float x) {
    float e = __expf(2.0f * x);
    return 1.0f - __fdividef(2.0f, e + 1.0f);
}
__device__ __forceinline__ unsigned long long fma2(unsigned long long a, unsigned long long b,
                                                   unsigned long long c) {
    unsigned long long d;
    asm("fma.rn.f32x2 %0, %1, %2, %3;" : "=l"(d) : "l"(a), "l"(b), "l"(c));
    return d;
}
__device__ __forceinline__ float hsum(unsigned long long a) {
    float lo, hi;
    asm("mov.b64 {%0, %1}, %2;" : "=f"(lo), "=f"(hi) : "l"(a));
    return lo + hi;
}

// ---------------------------------------------------------------------------
// i-paired triple-plane dot: acc{R,Z,N}[b] += sum_i w{R,Z,N}[j][i] * in[b][i]
// Weights: plane[j*SW + i], SW % 4 == 0, SW % 32 == 4 (conflict-free LDS.128).
// Inputs:  in[b*SI + i], broadcast loads.
template<int G, int SW, int SI>
__device__ __forceinline__ void dotacc(
    const float* __restrict__ pR, const float* __restrict__ pZ, const float* __restrict__ pN,
    const float* __restrict__ in, int j,
    unsigned long long aR[4], unsigned long long aZ[4], unsigned long long aN[4])
{
    const float* wR = pR + j * SW;
    const float* wZ = pZ + j * SW;
    const float* wN = pN + j * SW;
#pragma unroll
    for (int g = 0; g < G; ++g) {
        const int i0 = g * 4;
        ulonglong2 w0 = *(const ulonglong2*)(wR + i0);
        ulonglong2 w1 = *(const ulonglong2*)(wZ + i0);
        ulonglong2 w2 = *(const ulonglong2*)(wN + i0);
        ulonglong2 v0 = *(const ulonglong2*)(in + 0 * SI + i0);
        ulonglong2 v1 = *(const ulonglong2*)(in + 1 * SI + i0);
        ulonglong2 v2 = *(const ulonglong2*)(in + 2 * SI + i0);
        ulonglong2 v3 = *(const ulonglong2*)(in + 3 * SI + i0);
        aR[0] = fma2(w0.x, v0.x, aR[0]); aZ[0] = fma2(w1.x, v0.x, aZ[0]); aN[0] = fma2(w2.x, v0.x, aN[0]);
        aR[1] = fma2(w0.x, v1.x, aR[1]); aZ[1] = fma2(w1.x, v1.x, aZ[1]); aN[1] = fma2(w2.x, v1.x, aN[1]);
        aR[2] = fma2(w0.x, v2.x, aR[2]); aZ[2] = fma2(w1.x, v2.x, aZ[2]); aN[2] = fma2(w2.x, v2.x, aN[2]);
        aR[3] = fma2(w0.x, v3.x, aR[3]); aZ[3] = fma2(w1.x, v3.x, aZ[3]); aN[3] = fma2(w2.x, v3.x, aN[3]);
        aR[0] = fma2(w0.y, v0.y, aR[0]); aZ[0] = fma2(w1.y, v0.y, aZ[0]); aN[0] = fma2(w2.y, v0.y, aN[0]);
        aR[1] = fma2(w0.y, v1.y, aR[1]); aZ[1] = fma2(w1.y, v1.y, aZ[1]); aN[1] = fma2(w2.y, v1.y, aN[1]);
        aR[2] = fma2(w0.y, v2.y, aR[2]); aZ[2] = fma2(w1.y, v2.y, aZ[2]); aN[2] = fma2(w2.y, v2.y, aN[2]);
        aR[3] = fma2(w0.y, v3.y, aR[3]); aZ[3] = fma2(w1.y, v3.y, aZ[3]); aN[3] = fma2(w2.y, v3.y, aN[3]);
    }
}

// One GRU layer for 4 batches. st_h holds h^{t-1} on entry, h^t on exit.
template<int GI, int SWI, int SII>
__device__ __forceinline__ void gru_layer(
    const float* __restrict__ ihR, const float* __restrict__ ihZ, const float* __restrict__ ihN,
    const float* __restrict__ hhR, const float* __restrict__ hhZ, const float* __restrict__ hhN,
    const float* __restrict__ st_in, float* __restrict__ st_h,
    int j, float brc, float bzc, float bin, float bhn, float h[4])
{
    unsigned long long ar[4]  = {0,0,0,0}, az[4]  = {0,0,0,0};
    unsigned long long ani[4] = {0,0,0,0}, anh[4] = {0,0,0,0};
    dotacc<GI, SWI, SII>(ihR, ihZ, ihN, st_in, j, ar, az, ani);
    dotacc<8, 36, 32>(hhR, hhZ, hhN, st_h, j, ar, az, anh);
#pragma unroll
    for (int b = 0; b < 4; ++b) {
        float gr = sigm(hsum(ar[b]) + brc);
        float gz = sigm(hsum(az[b]) + bzc);
        float gn = tanh_f(hsum(ani[b]) + bin + gr * (hsum(anh[b]) + bhn));
        h[b] = gn + gz * (h[b] - gn);
    }
    __syncwarp();   // all reads of st_h done before overwrite
#pragma unroll
    for (int b = 0; b < 4; ++b) st_h[b * 32 + j] = h[b];
    __syncwarp();
}

// ---------------------------------------------------------------------------

__global__ void init_kernel() {
    int i = blockIdx.x * blockDim.x + threadIdx.x;
    if (i < Rn * 4) g_progress[i] = 0;
}

// ---------------------------------------------------------------------------
// Smem layout (floats). Planes: R, Z, N (gate-major).
#define PL_IH0   2176                  // 32*68
#define PL_SM    1152                  // 32*36
#define P_IH0    0                     // 3*2176 = 6528
#define P_HH0    6528
#define P_IH1    (6528 + 1*3456)
#define P_HH1    (6528 + 2*3456)
#define P_IH2    (6528 + 3*3456)
#define P_HH2    (6528 + 4*3456)
#define P_H2E    (6528 + 5*3456)       // 23808
#define P_STG    (6528 + 6*3456)       // 27264
#define STG_WARP 784                   // l0in 4*68=272, h0/h1/h2/pv 4*32=128 each
#define SM_FLOATS (P_STG + 4*STG_WARP) // 30400
#define SMEM_BYTES (SM_FLOATS * 4)     // 121600

extern __shared__ float s_rnn[];

__global__ __launch_bounds__(128, 1) void rnn_kernel(
    const int*   __restrict__ x,
    const float* __restrict__ emb,
    const float* __restrict__ wih0, const float* __restrict__ whh0,
    const float* __restrict__ bih0, const float* __restrict__ bhh0,
    const float* __restrict__ wih1, const float* __restrict__ whh1,
    const float* __restrict__ bih1, const float* __restrict__ bhh1,
    const float* __restrict__ wih2, const float* __restrict__ whh2,
    const float* __restrict__ bih2, const float* __restrict__ bhh2,
    const float* __restrict__ wh2e, const float* __restrict__ bh2e)
{
    const int r   = blockIdx.x;
    const int tid = threadIdx.x;

    // ---- zero smem (weight pads + staging init state) ----
    for (int n = tid; n < SM_FLOATS; n += 128) s_rnn[n] = 0.0f;
    __syncthreads();

    // ---- stage weights: global [gate*32+j][i] -> planes [p][j][i] ----
    for (int n = tid; n < 96 * 65; n += 128) {
        int gI = n / 65, i = n - gI * 65;
        s_rnn[P_IH0 + (gI >> 5) * PL_IH0 + (gI & 31) * 68 + i] = wih0[n];
    }
    {
        const float* srcs[5] = { whh0, wih1, whh1, wih2, whh2 };
        const int    offs[5] = { P_HH0, P_IH1, P_HH1, P_IH2, P_HH2 };
#pragma unroll
        for (int m = 0; m < 5; ++m) {
            const float* src = srcs[m];
            float* dst = s_rnn + offs[m];
            for (int n = tid; n < 96 * 32; n += 128) {
                int gI = n >> 5, i = n & 31;
                dst[(gI >> 5) * PL_SM + (gI & 31) * 36 + i] = src[n];
            }
        }
    }
    // h2e: [65][32]. P0 = rows 0..31, P1 = rows 32..63, P2 = row 64 replicated.
    for (int n = tid; n < 64 * 32; n += 128) {
        int e = n >> 5, hh = n & 31;
        s_rnn[P_H2E + (e >> 5) * PL_SM + (e & 31) * 36 + hh] = wh2e[n];
    }
    for (int n = tid; n < 32 * 32; n += 128) {
        int jj = n >> 5, hh = n & 31;
        s_rnn[P_H2E + 2 * PL_SM + jj * 36 + hh] = wh2e[64 * 32 + hh];
    }
    __syncthreads();

    const int g = tid >> 5;   // batch group: batches 4g..4g+3
    const int j = tid & 31;
    const int b0 = 4 * g;

    // plane pointers
    const float* ih0R = s_rnn + P_IH0;
    const float* ih0Z = ih0R + PL_IH0;
    const float* ih0N = ih0Z + PL_IH0;
    const float* hh0R = s_rnn + P_HH0, *hh0Z = hh0R + PL_SM, *hh0N = hh0Z + PL_SM;
    const float* ih1R = s_rnn + P_IH1, *ih1Z = ih1R + PL_SM, *ih1N = ih1Z + PL_SM;
    const float* hh1R = s_rnn + P_HH1, *hh1Z = hh1R + PL_SM, *hh1N = hh1Z + PL_SM;
    const float* ih2R = s_rnn + P_IH2, *ih2Z = ih2R + PL_SM, *ih2N = ih2Z + PL_SM;
    const float* hh2R = s_rnn + P_HH2, *hh2Z = hh2R + PL_SM, *hh2N = hh2Z + PL_SM;
    const float* heP0 = s_rnn + P_H2E, *heP1 = heP0 + PL_SM, *heP2 = heP1 + PL_SM;

    float* stg   = s_rnn + P_STG + g * STG_WARP;
    float* st_l0 = stg;            // [b*68 + i], i<65 written, 65..67 stay 0
    float* st_h0 = stg + 272;      // [b*32 + j]
    float* st_h1 = stg + 400;
    float* st_h2 = stg + 528;
    float* st_pv = stg + 656;

    // per-lane biases
    const float brc0 = bih0[j] + bhh0[j], bzc0 = bih0[32+j] + bhh0[32+j];
    const float bin0 = bih0[64+j],        bhn0 = bhh0[64+j];
    const float brc1 = bih1[j] + bhh1[j], bzc1 = bih1[32+j] + bhh1[32+j];
    const float bin1 = bih1[64+j],        bhn1 = bhh1[64+j];
    const float brc2 = bih2[j] + bhh2[j], bzc2 = bih2[32+j] + bhh2[32+j];
    const float bin2 = bih2[64+j],        bhn2 = bhh2[64+j];
    const float be0 = bh2e[j], be1 = bh2e[32 + j], be2 = bh2e[64];

    const float rf = (float)r * (2.0f / 128.0f) - 1.0f;
    const float c2base = rf + be2;

    int* myflag = &g_progress[r * 4 + g];
    const int* waitflag = (r > 0) ? &g_progress[(r - 1) * 4 + g] : (const int*)0;

    float h0[4] = {0,0,0,0}, h1[4] = {0,0,0,0}, h2[4] = {0,0,0,0};

    for (int t = 0; t < Tn; ++t) {
        // ---- embedding (independent of flag; issue early) ----
        float e0[4], e1[4];
#pragma unroll
        for (int b = 0; b < 4; ++b) {
            int xv = x[((b0 + b) * Rn + r) * Tn + t];
            e0[b] = emb[xv * En + j];
            e1[b] = emb[xv * En + 32 + j];
        }

        float c0[4], c1[4], c2[4];
        if (r > 0) {
            while (ld_acq(waitflag) <= t) { }
#pragma unroll
            for (int b = 0; b < 4; ++b) {
                float pv = __ldcg(&g_out_h[(size_t)(((b0 + b) * Rn + (r - 1)) * Tn + t) * Hn + j]);
                st_pv[b * 32 + j] = pv;
            }
            __syncwarp();
            unsigned long long a0[4] = {0,0,0,0}, a1[4] = {0,0,0,0}, a2[4] = {0,0,0,0};
            dotacc<8, 36, 32>(heP0, heP1, heP2, st_pv, j, a0, a1, a2);
#pragma unroll
            for (int b = 0; b < 4; ++b) {
                c0[b] = e0[b] + be0 + hsum(a0[b]);
                c1[b] = e1[b] + be1 + hsum(a1[b]);
                c2[b] = c2base + hsum(a2[b]);
            }
        } else {
#pragma unroll
            for (int b = 0; b < 4; ++b) {
                c0[b] = e0[b] + be0;
                c1[b] = e1[b] + be1;
                c2[b] = c2base;
            }
        }

        // stage layer-0 input vector [c0(0..31) | c1(32..63) | c2(64) | 0 0 0]
#pragma unroll
        for (int b = 0; b < 4; ++b) {
            st_l0[b * 68 + j]      = c0[b];
            st_l0[b * 68 + 32 + j] = c1[b];
        }
        if (j == 0) {
#pragma unroll
            for (int b = 0; b < 4; ++b) st_l0[b * 68 + 64] = c2[b];
        }
        __syncwarp();

        gru_layer<17, 68, 68>(ih0R, ih0Z, ih0N, hh0R, hh0Z, hh0N,
                              st_l0, st_h0, j, brc0, bzc0, bin0, bhn0, h0);
        gru_layer<8, 36, 32>(ih1R, ih1Z, ih1N, hh1R, hh1Z, hh1N,
                             st_h0, st_h1, j, brc1, bzc1, bin1, bhn1, h1);
        gru_layer<8, 36, 32>(ih2R, ih2Z, ih2N, hh2R, hh2Z, hh2N,
                             st_h1, st_h2, j, brc2, bzc2, bin2, bhn2, h2);

        // ---- publish top-layer output + release flag ----
#pragma unroll
        for (int b = 0; b < 4; ++b)
            __stcg(&g_out_h[(size_t)(((b0 + b) * Rn + r) * Tn + t) * Hn + j], h2[b]);
        __syncwarp();
        if (j == 0) {
            __threadfence();
            asm volatile("st.global.release.gpu.b32 [%0], %1;" :: "l"(myflag), "r"(t + 1) : "memory");
        }
    }
}

// ---------------------------------------------------------------------------
// Output projection: pred[n][v] = sum_h out_h[n][h] * w_out[v][h] + b_out[v]
#define PROJ_TOK 64

__global__ __launch_bounds__(256) void proj_kernel(
    const float* __restrict__ w_out,
    const float* __restrict__ b_out,
    float* __restrict__ pred)
{
    __shared__ float w_s[32 * 260];
    __shared__ float h_s[PROJ_TOK * 32];
    __shared__ float b_s[260];

    const int tid = threadIdx.x;

    for (int n = tid; n < VOCABn * 32; n += 256) {
        int v = n >> 5, h = n & 31;
        w_s[h * 260 + v] = w_out[n];
    }
    for (int n = tid; n < VOCABn; n += 256) b_s[n] = b_out[n];
    if (tid < 2) b_s[VOCABn + tid] = 0.0f;

    const size_t tok0 = (size_t)blockIdx.x * PROJ_TOK;
    const float* src = g_out_h + tok0 * 32;
    for (int n = tid; n < PROJ_TOK * 32; n += 256) h_s[n] = src[n];
    __syncthreads();

    for (int idx = tid; idx < PROJ_TOK * 129; idx += 256) {
        int tok = idx / 129;
        int p   = idx - tok * 129;
        unsigned long long acc = *(const unsigned long long*)&b_s[2 * p];
        const float* hs = &h_s[tok * 32];
        const unsigned long long* wp = (const unsigned long long*)&w_s[2 * p];
#pragma unroll
        for (int h = 0; h < 32; ++h) {
            float hv = hs[h];
            unsigned long long w2 = wp[(size_t)h * 130];
            unsigned long long hp;
            asm("mov.b64 %0, {%1, %1};" : "=l"(hp) : "f"(hv));
            acc = fma2(w2, hp, acc);
        }
        *(unsigned long long*)&pred[(tok0 + (size_t)tok) * VOCABn + 2 * p] = acc;
    }
}

// ---------------------------------------------------------------------------

extern "C" void kernel_launch(void* const* d_in, const int* in_sizes, int n_in,
                              void* d_out, int out_size)
{
    const int*   x     = (const int*)  d_in[0];
    const float* emb   = (const float*)d_in[1];
    const float* wih0  = (const float*)d_in[2];
    const float* whh0  = (const float*)d_in[3];
    const float* bih0  = (const float*)d_in[4];
    const float* bhh0  = (const float*)d_in[5];
    const float* wih1  = (const float*)d_in[6];
    const float* whh1  = (const float*)d_in[7];
    const float* bih1  = (const float*)d_in[8];
    const float* bhh1  = (const float*)d_in[9];
    const float* wih2  = (const float*)d_in[10];
    const float* whh2  = (const float*)d_in[11];
    const float* bih2  = (const float*)d_in[12];
    const float* bhh2  = (const float*)d_in[13];
    const float* wh2e  = (const float*)d_in[14];
    const float* bh2e  = (const float*)d_in[15];
    const float* w_out = (const float*)d_in[16];
    const float* b_out = (const float*)d_in[17];
    float* pred = (float*)d_out;

    cudaFuncSetAttribute(rnn_kernel, cudaFuncAttributeMaxDynamicSharedMemorySize, SMEM_BYTES);

    init_kernel<<<1, 512>>>();
    rnn_kernel<<<Rn, 128, SMEM_BYTES>>>(x, emb,
        wih0, whh0, bih0, bhh0,
        wih1, whh1, bih1, bhh1,
        wih2, whh2, bih2, bhh2,
        wh2e, bh2e);
    proj_kernel<<<NTOK / PROJ_TOK, 256>>>(w_out, b_out, pred);
}

// round 8
// speedup vs baseline: 1.7858x; 1.5908x over previous
#include <cuda_runtime.h>

// Problem constants
#define Bn     16
#define Rn     128
#define Tn     128
#define Hn     32
#define En     64
#define VOCABn 258
#define NTOK   (Bn*Rn*Tn)   // 262144

// Scratch: top-layer GRU outputs [b][r][t][h], and per-(row,group) progress flags.
__device__ float g_out_h[(size_t)NTOK * Hn];
__device__ int   g_progress[Rn * 4];   // zero-initialized; reset by proj_kernel each run

// ---------------------------------------------------------------------------

__device__ __forceinline__ int ld_acq(const int* p) {
    int v;
    asm volatile("ld.global.acquire.gpu.b32 %0, [%1];" : "=r"(v) : "l"(p) : "memory");
    return v;
}
__device__ __forceinline__ void st_rel(int* p, int v) {
    asm volatile("st.global.release.gpu.b32 [%0], %1;" :: "l"(p), "r"(v) : "memory");
}
__device__ __forceinline__ float sigm(float x) {
    return __fdividef(1.0f, 1.0f + __expf(-x));
}
__device__ __forceinline__ float tanh_f(float x) {
    float e = __expf(2.0f * x);
    return 1.0f - __fdividef(2.0f, e + 1.0f);
}
__device__ __forceinline__ unsigned long long fma2(unsigned long long a, unsigned long long b,
                                                   unsigned long long c) {
    unsigned long long d;
    asm("fma.rn.f32x2 %0, %1, %2, %3;" : "=l"(d) : "l"(a), "l"(b), "l"(c));
    return d;
}
__device__ __forceinline__ float hsum(unsigned long long a) {
    float lo, hi;
    asm("mov.b64 {%0, %1}, %2;" : "=f"(lo), "=f"(hi) : "l"(a));
    return lo + hi;
}

// ---------------------------------------------------------------------------
// i-paired triple-plane dot: acc{R,Z,N}[b] += sum_i w{R,Z,N}[j][i] * in[b][i]
// Weights: plane[j*SW + i], SW % 4 == 0, SW % 32 == 4 (conflict-free LDS.128
// in 8-lane phases). Inputs: in[b*SI + i], broadcast loads.
template<int G, int SW, int SI>
__device__ __forceinline__ void dotacc(
    const float* __restrict__ pR, const float* __restrict__ pZ, const float* __restrict__ pN,
    const float* __restrict__ in, int j,
    unsigned long long aR[4], unsigned long long aZ[4], unsigned long long aN[4])
{
    const float* wR = pR + j * SW;
    const float* wZ = pZ + j * SW;
    const float* wN = pN + j * SW;
#pragma unroll
    for (int g = 0; g < G; ++g) {
        const int i0 = g * 4;
        ulonglong2 w0 = *(const ulonglong2*)(wR + i0);
        ulonglong2 w1 = *(const ulonglong2*)(wZ + i0);
        ulonglong2 w2 = *(const ulonglong2*)(wN + i0);
        ulonglong2 v0 = *(const ulonglong2*)(in + 0 * SI + i0);
        ulonglong2 v1 = *(const ulonglong2*)(in + 1 * SI + i0);
        ulonglong2 v2 = *(const ulonglong2*)(in + 2 * SI + i0);
        ulonglong2 v3 = *(const ulonglong2*)(in + 3 * SI + i0);
        aR[0] = fma2(w0.x, v0.x, aR[0]); aZ[0] = fma2(w1.x, v0.x, aZ[0]); aN[0] = fma2(w2.x, v0.x, aN[0]);
        aR[1] = fma2(w0.x, v1.x, aR[1]); aZ[1] = fma2(w1.x, v1.x, aZ[1]); aN[1] = fma2(w2.x, v1.x, aN[1]);
        aR[2] = fma2(w0.x, v2.x, aR[2]); aZ[2] = fma2(w1.x, v2.x, aZ[2]); aN[2] = fma2(w2.x, v2.x, aN[2]);
        aR[3] = fma2(w0.x, v3.x, aR[3]); aZ[3] = fma2(w1.x, v3.x, aZ[3]); aN[3] = fma2(w2.x, v3.x, aN[3]);
        aR[0] = fma2(w0.y, v0.y, aR[0]); aZ[0] = fma2(w1.y, v0.y, aZ[0]); aN[0] = fma2(w2.y, v0.y, aN[0]);
        aR[1] = fma2(w0.y, v1.y, aR[1]); aZ[1] = fma2(w1.y, v1.y, aZ[1]); aN[1] = fma2(w2.y, v1.y, aN[1]);
        aR[2] = fma2(w0.y, v2.y, aR[2]); aZ[2] = fma2(w1.y, v2.y, aZ[2]); aN[2] = fma2(w2.y, v2.y, aN[2]);
        aR[3] = fma2(w0.y, v3.y, aR[3]); aZ[3] = fma2(w1.y, v3.y, aZ[3]); aN[3] = fma2(w2.y, v3.y, aN[3]);
    }
}

// One GRU layer for 4 batches. st_h holds h^{t-1} on entry, h^t on exit.
template<int GI, int SWI, int SII>
__device__ __forceinline__ void gru_layer(
    const float* __restrict__ ihR, const float* __restrict__ ihZ, const float* __restrict__ ihN,
    const float* __restrict__ hhR, const float* __restrict__ hhZ, const float* __restrict__ hhN,
    const float* __restrict__ st_in, float* __restrict__ st_h,
    int j, float brc, float bzc, float bin, float bhn, float h[4])
{
    unsigned long long ar[4]  = {0,0,0,0}, az[4]  = {0,0,0,0};
    unsigned long long ani[4] = {0,0,0,0}, anh[4] = {0,0,0,0};
    dotacc<GI, SWI, SII>(ihR, ihZ, ihN, st_in, j, ar, az, ani);
    dotacc<8, 36, 32>(hhR, hhZ, hhN, st_h, j, ar, az, anh);
#pragma unroll
    for (int b = 0; b < 4; ++b) {
        float gr = sigm(hsum(ar[b]) + brc);
        float gz = sigm(hsum(az[b]) + bzc);
        float gn = tanh_f(hsum(ani[b]) + bin + gr * (hsum(anh[b]) + bhn));
        h[b] = gn + gz * (h[b] - gn);
    }
    __syncwarp();
#pragma unroll
    for (int b = 0; b < 4; ++b) st_h[b * 32 + j] = h[b];
    __syncwarp();
}

// ---------------------------------------------------------------------------
// Smem layout (floats). Planes: R, Z, N (gate-major).
#define PL_IH0   2176                  // 32*68
#define PL_SM    1152                  // 32*36
#define P_IH0    0                     // 3*2176 = 6528
#define P_HH0    6528
#define P_IH1    (6528 + 1*3456)
#define P_HH1    (6528 + 2*3456)
#define P_IH2    (6528 + 3*3456)
#define P_HH2    (6528 + 4*3456)
#define P_M      (6528 + 5*3456)       // folded W_ih0 @ W_h2e^T, staged like hh
#define P_STG    (6528 + 6*3456)       // 27264
#define STG_WARP 768                   // l0in 4*64=256, h0/h1/h2/pv 4*32=128 each
#define P_BF     (P_STG + 4*STG_WARP)  // folded layer-0 gate bias [96]
#define SM_FLOATS (P_BF + 128)
#define SMEM_BYTES (SM_FLOATS * 4)

extern __shared__ float s_rnn[];

__global__ __launch_bounds__(128, 1) void rnn_kernel(
    const int*   __restrict__ x,
    const float* __restrict__ emb,
    const float* __restrict__ wih0, const float* __restrict__ whh0,
    const float* __restrict__ bih0, const float* __restrict__ bhh0,
    const float* __restrict__ wih1, const float* __restrict__ whh1,
    const float* __restrict__ bih1, const float* __restrict__ bhh1,
    const float* __restrict__ wih2, const float* __restrict__ whh2,
    const float* __restrict__ bih2, const float* __restrict__ bhh2,
    const float* __restrict__ wh2e, const float* __restrict__ bh2e)
{
    const int r   = blockIdx.x;
    const int tid = threadIdx.x;
    const float rf = (float)r * (2.0f / 128.0f) - 1.0f;

    // ---- zero smem (weight pads + staging init state) ----
    for (int n = tid; n < SM_FLOATS; n += 128) s_rnn[n] = 0.0f;
    __syncthreads();

    // ---- stage weights: global [gate*32+j][i] -> planes [p][j][i] ----
    for (int n = tid; n < 96 * 65; n += 128) {
        int gI = n / 65, i = n - gI * 65;
        s_rnn[P_IH0 + (gI >> 5) * PL_IH0 + (gI & 31) * 68 + i] = wih0[n];
    }
    {
        const float* srcs[5] = { whh0, wih1, whh1, wih2, whh2 };
        const int    offs[5] = { P_HH0, P_IH1, P_HH1, P_IH2, P_HH2 };
#pragma unroll
        for (int m = 0; m < 5; ++m) {
            const float* src = srcs[m];
            float* dst = s_rnn + offs[m];
            for (int n = tid; n < 96 * 32; n += 128) {
                int gI = n >> 5, i = n & 31;
                dst[(gI >> 5) * PL_SM + (gI & 31) * 36 + i] = src[n];
            }
        }
    }
    // ---- fold: M[g][h] = sum_e wih0[g][e] * wh2e[e][h]  (e over all 65) ----
    for (int n = tid; n < 96 * 32; n += 128) {
        int gI = n >> 5, h = n & 31;
        const float* wr = wih0 + gI * 65;
        float acc = wr[64] * __ldg(&wh2e[64 * 32 + h]);
#pragma unroll 4
        for (int e = 0; e < 64; ++e) acc += wr[e] * __ldg(&wh2e[e * 32 + h]);
        s_rnn[P_M + (gI >> 5) * PL_SM + (gI & 31) * 36 + h] = acc;
    }
    // ---- fold: bf[g] = bih0[g] + sum_e wih0[g][e]*bh2e[e] + wih0[g][64]*rf ----
    if (tid < 96) {
        const float* wr = wih0 + tid * 65;
        float acc = bih0[tid] + wr[64] * rf;
#pragma unroll 5
        for (int e = 0; e < 65; ++e) acc += wr[e] * __ldg(&bh2e[e]);
        s_rnn[P_BF + tid] = acc;
    }
    __syncthreads();

    const int g = tid >> 5;   // batch group: batches 4g..4g+3
    const int j = tid & 31;
    const int b0 = 4 * g;

    const float* ih0R = s_rnn + P_IH0;
    const float* ih0Z = ih0R + PL_IH0;
    const float* ih0N = ih0Z + PL_IH0;
    const float* hh0R = s_rnn + P_HH0, *hh0Z = hh0R + PL_SM, *hh0N = hh0Z + PL_SM;
    const float* ih1R = s_rnn + P_IH1, *ih1Z = ih1R + PL_SM, *ih1N = ih1Z + PL_SM;
    const float* hh1R = s_rnn + P_HH1, *hh1Z = hh1R + PL_SM, *hh1N = hh1Z + PL_SM;
    const float* ih2R = s_rnn + P_IH2, *ih2Z = ih2R + PL_SM, *ih2N = ih2Z + PL_SM;
    const float* hh2R = s_rnn + P_HH2, *hh2Z = hh2R + PL_SM, *hh2N = hh2Z + PL_SM;
    const float* MR   = s_rnn + P_M,   *MZ   = MR + PL_SM,   *MN   = MZ + PL_SM;

    float* stg   = s_rnn + P_STG + g * STG_WARP;
    float* st_l0 = stg;            // [b*64 + i]
    float* st_h0 = stg + 256;      // [b*32 + j]
    float* st_h1 = stg + 384;
    float* st_h2 = stg + 512;
    float* st_pv = stg + 640;

    // per-lane biases (layer-0 ih biases folded with b_h2e + rf)
    const float brc0 = s_rnn[P_BF + j]      + bhh0[j];
    const float bzc0 = s_rnn[P_BF + 32 + j] + bhh0[32 + j];
    const float bin0 = s_rnn[P_BF + 64 + j];
    const float bhn0 = bhh0[64 + j];
    const float brc1 = bih1[j] + bhh1[j], bzc1 = bih1[32+j] + bhh1[32+j];
    const float bin1 = bih1[64+j],        bhn1 = bhh1[64+j];
    const float brc2 = bih2[j] + bhh2[j], bzc2 = bih2[32+j] + bhh2[32+j];
    const float bin2 = bih2[64+j],        bhn2 = bhh2[64+j];

    int* myflag = &g_progress[r * 4 + g];
    const int* waitflag = (r > 0) ? &g_progress[(r - 1) * 4 + g] : (const int*)0;

    float h0[4] = {0,0,0,0}, h1[4] = {0,0,0,0}, h2[4] = {0,0,0,0};

    // ---- prefetch t=0 embeddings ----
    float e0c[4], e1c[4];
    {
        int xv[4];
#pragma unroll
        for (int b = 0; b < 4; ++b) xv[b] = __ldg(&x[((b0 + b) * Rn + r) * Tn]);
#pragma unroll
        for (int b = 0; b < 4; ++b) {
            e0c[b] = __ldg(&emb[xv[b] * En + j]);
            e1c[b] = __ldg(&emb[xv[b] * En + 32 + j]);
        }
    }

    for (int t = 0; t < Tn; ++t) {
        // 1. issue next-t x gathers (DRAM latency hidden under this cell)
        const int tnx = (t + 1 < Tn) ? t + 1 : t;
        int xn[4];
#pragma unroll
        for (int b = 0; b < 4; ++b) xn[b] = __ldg(&x[((b0 + b) * Rn + r) * Tn + tnx]);

        // 2. stage layer-0 input (pure embedding; biases/rf folded)
#pragma unroll
        for (int b = 0; b < 4; ++b) {
            st_l0[b * 64 + j]      = e0c[b];
            st_l0[b * 64 + 32 + j] = e1c[b];
        }
        __syncwarp();

        // 3. layer-0 dots that do NOT depend on previous row
        unsigned long long ar[4]  = {0,0,0,0}, az[4]  = {0,0,0,0};
        unsigned long long ani[4] = {0,0,0,0}, anh[4] = {0,0,0,0};
        dotacc<16, 68, 64>(ih0R, ih0Z, ih0N, st_l0, j, ar, az, ani);
        dotacc<8, 36, 32>(hh0R, hh0Z, hh0N, st_h0, j, ar, az, anh);

        // 4. next-t emb gathers (x(t+1) has landed by now)
        float e0n[4], e1n[4];
#pragma unroll
        for (int b = 0; b < 4; ++b) {
            e0n[b] = __ldg(&emb[xn[b] * En + j]);
            e1n[b] = __ldg(&emb[xn[b] * En + 32 + j]);
        }

        // 5. previous-row coupling: short 32-dot through folded M
        if (r > 0) {
            while (ld_acq(waitflag) <= t) { }
#pragma unroll
            for (int b = 0; b < 4; ++b)
                st_pv[b * 32 + j] = __ldcg(&g_out_h[(size_t)(((b0 + b) * Rn + (r - 1)) * Tn + t) * Hn + j]);
            __syncwarp();
            dotacc<8, 36, 32>(MR, MZ, MN, st_pv, j, ar, az, ani);
        }

        // 6. layer-0 activations
#pragma unroll
        for (int b = 0; b < 4; ++b) {
            float gr = sigm(hsum(ar[b]) + brc0);
            float gz = sigm(hsum(az[b]) + bzc0);
            float gn = tanh_f(hsum(ani[b]) + bin0 + gr * (hsum(anh[b]) + bhn0));
            h0[b] = gn + gz * (h0[b] - gn);
        }
        __syncwarp();
#pragma unroll
        for (int b = 0; b < 4; ++b) st_h0[b * 32 + j] = h0[b];
        __syncwarp();

        // 7. layers 1, 2
        gru_layer<8, 36, 32>(ih1R, ih1Z, ih1N, hh1R, hh1Z, hh1N,
                             st_h0, st_h1, j, brc1, bzc1, bin1, bhn1, h1);
        gru_layer<8, 36, 32>(ih2R, ih2Z, ih2N, hh2R, hh2Z, hh2N,
                             st_h1, st_h2, j, brc2, bzc2, bin2, bhn2, h2);

        // 8. publish + release (all lanes release the same flag: each lane's
        //    own h2 stores are ordered before its own release store)
#pragma unroll
        for (int b = 0; b < 4; ++b)
            __stcg(&g_out_h[(size_t)(((b0 + b) * Rn + r) * Tn + t) * Hn + j], h2[b]);
        st_rel(myflag, t + 1);

        // rotate prefetch
#pragma unroll
        for (int b = 0; b < 4; ++b) { e0c[b] = e0n[b]; e1c[b] = e1n[b]; }
    }
}

// ---------------------------------------------------------------------------
// Output projection: pred[n][v] = sum_h out_h[n][h] * w_out[v][h] + b_out[v]
// Also resets the progress flags for the next replay (stream-ordered).
#define PROJ_TOK 64

__global__ __launch_bounds__(256) void proj_kernel(
    const float* __restrict__ w_out,
    const float* __restrict__ b_out,
    float* __restrict__ pred)
{
    __shared__ float w_s[32 * 260];
    __shared__ float h_s[PROJ_TOK * 32];
    __shared__ float b_s[260];

    const int tid = threadIdx.x;

    if (blockIdx.x == 0) {
        for (int n = tid; n < Rn * 4; n += 256) g_progress[n] = 0;
    }

    for (int n = tid; n < VOCABn * 32; n += 256) {
        int v = n >> 5, h = n & 31;
        w_s[h * 260 + v] = w_out[n];
    }
    for (int n = tid; n < VOCABn; n += 256) b_s[n] = b_out[n];
    if (tid < 2) b_s[VOCABn + tid] = 0.0f;

    const size_t tok0 = (size_t)blockIdx.x * PROJ_TOK;
    const float* src = g_out_h + tok0 * 32;
    for (int n = tid; n < PROJ_TOK * 32; n += 256) h_s[n] = src[n];
    __syncthreads();

    for (int idx = tid; idx < PROJ_TOK * 129; idx += 256) {
        int tok = idx / 129;
        int p   = idx - tok * 129;
        unsigned long long acc = *(const unsigned long long*)&b_s[2 * p];
        const float* hs = &h_s[tok * 32];
        const unsigned long long* wp = (const unsigned long long*)&w_s[2 * p];
#pragma unroll
        for (int h = 0; h < 32; ++h) {
            float hv = hs[h];
            unsigned long long w2 = wp[(size_t)h * 130];
            unsigned long long hp;
            asm("mov.b64 %0, {%1, %1};" : "=l"(hp) : "f"(hv));
            acc = fma2(w2, hp, acc);
        }
        *(unsigned long long*)&pred[(tok0 + (size_t)tok) * VOCABn + 2 * p] = acc;
    }
}

// ---------------------------------------------------------------------------

extern "C" void kernel_launch(void* const* d_in, const int* in_sizes, int n_in,
                              void* d_out, int out_size)
{
    const int*   x     = (const int*)  d_in[0];
    const float* emb   = (const float*)d_in[1];
    const float* wih0  = (const float*)d_in[2];
    const float* whh0  = (const float*)d_in[3];
    const float* bih0  = (const float*)d_in[4];
    const float* bhh0  = (const float*)d_in[5];
    const float* wih1  = (const float*)d_in[6];
    const float* whh1  = (const float*)d_in[7];
    const float* bih1  = (const float*)d_in[8];
    const float* bhh1  = (const float*)d_in[9];
    const float* wih2  = (const float*)d_in[10];
    const float* whh2  = (const float*)d_in[11];
    const float* bih2  = (const float*)d_in[12];
    const float* bhh2  = (const float*)d_in[13];
    const float* wh2e  = (const float*)d_in[14];
    const float* bh2e  = (const float*)d_in[15];
    const float* w_out = (const float*)d_in[16];
    const float* b_out = (const float*)d_in[17];
    float* pred = (float*)d_out;

    cudaFuncSetAttribute(rnn_kernel, cudaFuncAttributeMaxDynamicSharedMemorySize, SMEM_BYTES);

    rnn_kernel<<<Rn, 128, SMEM_BYTES>>>(x, emb,
        wih0, whh0, bih0, bhh0,
        wih1, whh1, bih1, bhh1,
        wih2, whh2, bih2, bhh2,
        wh2e, bh2e);
    proj_kernel<<<NTOK / PROJ_TOK, 256>>>(w_out, b_out, pred);
}

// round 9
// speedup vs baseline: 2.0947x; 1.1730x over previous
#include <cuda_runtime.h>

// Problem constants
#define Bn     16
#define Rn     128
#define Tn     128
#define Hn     32
#define En     64
#define VOCABn 258
#define NTOK   (Bn*Rn*Tn)   // 262144

// Scratch
__device__ float g_out_h[(size_t)NTOK * Hn];
__device__ int   g_progress[Rn * 4];     // reset by proj_kernel for next replay
__device__ float g_G[VOCABn * 96];       // W_ih0[:, :64] @ embed_table[v]^T

// ---------------------------------------------------------------------------

__device__ __forceinline__ int ld_acq(const int* p) {
    int v;
    asm volatile("ld.global.acquire.gpu.b32 %0, [%1];" : "=r"(v) : "l"(p) : "memory");
    return v;
}
__device__ __forceinline__ void st_rel(int* p, int v) {
    asm volatile("st.global.release.gpu.b32 [%0], %1;" :: "l"(p), "r"(v) : "memory");
}
__device__ __forceinline__ float sigm(float x) {
    return __fdividef(1.0f, 1.0f + __expf(-x));
}
__device__ __forceinline__ float tanh_f(float x) {
    float e = __expf(2.0f * x);
    return 1.0f - __fdividef(2.0f, e + 1.0f);
}
__device__ __forceinline__ unsigned long long fma2(unsigned long long a, unsigned long long b,
                                                   unsigned long long c) {
    unsigned long long d;
    asm("fma.rn.f32x2 %0, %1, %2, %3;" : "=l"(d) : "l"(a), "l"(b), "l"(c));
    return d;
}
__device__ __forceinline__ unsigned long long dup2(float v) {
    unsigned long long d;
    asm("mov.b64 %0, {%1, %1};" : "=l"(d) : "f"(v));
    return d;
}
__device__ __forceinline__ float hsum(unsigned long long a) {
    float lo, hi;
    asm("mov.b64 {%0, %1}, %2;" : "=f"(lo), "=f"(hi) : "l"(a));
    return lo + hi;
}

// ---------------------------------------------------------------------------
// i-paired triple-plane dot (32-wide): acc{R,Z,N}[b] += sum_i w{p}[j][i]*in[b][i]
template<int G, int SW, int SI>
__device__ __forceinline__ void dotacc(
    const float* __restrict__ pR, const float* __restrict__ pZ, const float* __restrict__ pN,
    const float* __restrict__ in, int j,
    unsigned long long aR[4], unsigned long long aZ[4], unsigned long long aN[4])
{
    const float* wR = pR + j * SW;
    const float* wZ = pZ + j * SW;
    const float* wN = pN + j * SW;
#pragma unroll
    for (int g = 0; g < G; ++g) {
        const int i0 = g * 4;
        ulonglong2 w0 = *(const ulonglong2*)(wR + i0);
        ulonglong2 w1 = *(const ulonglong2*)(wZ + i0);
        ulonglong2 w2 = *(const ulonglong2*)(wN + i0);
        ulonglong2 v0 = *(const ulonglong2*)(in + 0 * SI + i0);
        ulonglong2 v1 = *(const ulonglong2*)(in + 1 * SI + i0);
        ulonglong2 v2 = *(const ulonglong2*)(in + 2 * SI + i0);
        ulonglong2 v3 = *(const ulonglong2*)(in + 3 * SI + i0);
        aR[0] = fma2(w0.x, v0.x, aR[0]); aZ[0] = fma2(w1.x, v0.x, aZ[0]); aN[0] = fma2(w2.x, v0.x, aN[0]);
        aR[1] = fma2(w0.x, v1.x, aR[1]); aZ[1] = fma2(w1.x, v1.x, aZ[1]); aN[1] = fma2(w2.x, v1.x, aN[1]);
        aR[2] = fma2(w0.x, v2.x, aR[2]); aZ[2] = fma2(w1.x, v2.x, aZ[2]); aN[2] = fma2(w2.x, v2.x, aN[2]);
        aR[3] = fma2(w0.x, v3.x, aR[3]); aZ[3] = fma2(w1.x, v3.x, aZ[3]); aN[3] = fma2(w2.x, v3.x, aN[3]);
        aR[0] = fma2(w0.y, v0.y, aR[0]); aZ[0] = fma2(w1.y, v0.y, aZ[0]); aN[0] = fma2(w2.y, v0.y, aN[0]);
        aR[1] = fma2(w0.y, v1.y, aR[1]); aZ[1] = fma2(w1.y, v1.y, aZ[1]); aN[1] = fma2(w2.y, v1.y, aN[1]);
        aR[2] = fma2(w0.y, v2.y, aR[2]); aZ[2] = fma2(w1.y, v2.y, aZ[2]); aN[2] = fma2(w2.y, v2.y, aN[2]);
        aR[3] = fma2(w0.y, v3.y, aR[3]); aZ[3] = fma2(w1.y, v3.y, aZ[3]); aN[3] = fma2(w2.y, v3.y, aN[3]);
    }
}

template<int GI, int SWI, int SII>
__device__ __forceinline__ void gru_layer(
    const float* __restrict__ ihR, const float* __restrict__ ihZ, const float* __restrict__ ihN,
    const float* __restrict__ hhR, const float* __restrict__ hhZ, const float* __restrict__ hhN,
    const float* __restrict__ st_in, float* __restrict__ st_h,
    int j, float brc, float bzc, float bin, float bhn, float h[4])
{
    unsigned long long ar[4]  = {0,0,0,0}, az[4]  = {0,0,0,0};
    unsigned long long ani[4] = {0,0,0,0}, anh[4] = {0,0,0,0};
    dotacc<GI, SWI, SII>(ihR, ihZ, ihN, st_in, j, ar, az, ani);
    dotacc<8, 36, 32>(hhR, hhZ, hhN, st_h, j, ar, az, anh);
#pragma unroll
    for (int b = 0; b < 4; ++b) {
        float gr = sigm(hsum(ar[b]) + brc);
        float gz = sigm(hsum(az[b]) + bzc);
        float gn = tanh_f(hsum(ani[b]) + bin + gr * (hsum(anh[b]) + bhn));
        h[b] = gn + gz * (h[b] - gn);
    }
    __syncwarp();
#pragma unroll
    for (int b = 0; b < 4; ++b) st_h[b * 32 + j] = h[b];
    __syncwarp();
}

// ---------------------------------------------------------------------------
// prep: G[v][g] = sum_e wih0[g][e] * embed_table[v][e]
__global__ void prep_kernel(const float* __restrict__ wih0,
                            const float* __restrict__ emb)
{
    const int v = blockIdx.x;
    const int g = threadIdx.x;    // 96 threads
    const float* wr = wih0 + g * 65;
    const float* er = emb + v * En;
    float acc = 0.0f;
#pragma unroll 8
    for (int e = 0; e < En; ++e) acc += wr[e] * er[e];
    g_G[v * 96 + g] = acc;
}

// ---------------------------------------------------------------------------
// Smem layout (floats). Planes: R, Z, N per matrix, row stride 36.
#define PL_SM    1152                  // 32*36
#define P_HH0    0
#define P_IH1    (1*3456)
#define P_HH1    (2*3456)
#define P_IH2    (3*3456)
#define P_HH2    (4*3456)
#define P_M      (5*3456)              // folded W_ih0 @ W_h2e^T
#define P_STG    (6*3456)              // 20736
#define STG_WARP 512                   // h0/h1/h2/pv: 4*32 each
#define P_BF     (P_STG + 4*STG_WARP)  // folded layer-0 gate bias [96]
#define SM_FLOATS (P_BF + 128)
#define SMEM_BYTES (SM_FLOATS * 4)     // ~91.6 KB

extern __shared__ float s_rnn[];

__global__ __launch_bounds__(128, 1) void rnn_kernel(
    const int*   __restrict__ x,
    const float* __restrict__ wih0, const float* __restrict__ whh0,
    const float* __restrict__ bih0, const float* __restrict__ bhh0,
    const float* __restrict__ wih1, const float* __restrict__ whh1,
    const float* __restrict__ bih1, const float* __restrict__ bhh1,
    const float* __restrict__ wih2, const float* __restrict__ whh2,
    const float* __restrict__ bih2, const float* __restrict__ bhh2,
    const float* __restrict__ wh2e, const float* __restrict__ bh2e)
{
    const int r   = blockIdx.x;
    const int tid = threadIdx.x;
    const float rf = (float)r * (2.0f / 128.0f) - 1.0f;

    for (int n = tid; n < SM_FLOATS; n += 128) s_rnn[n] = 0.0f;
    __syncthreads();

    // stage recurrent weights into gate planes
    {
        const float* srcs[5] = { whh0, wih1, whh1, wih2, whh2 };
        const int    offs[5] = { P_HH0, P_IH1, P_HH1, P_IH2, P_HH2 };
#pragma unroll
        for (int m = 0; m < 5; ++m) {
            const float* src = srcs[m];
            float* dst = s_rnn + offs[m];
            for (int n = tid; n < 96 * 32; n += 128) {
                int gI = n >> 5, i = n & 31;
                dst[(gI >> 5) * PL_SM + (gI & 31) * 36 + i] = src[n];
            }
        }
    }
    // fold M[g][h] = sum_e wih0[g][e] * wh2e[e][h]
    for (int n = tid; n < 96 * 32; n += 128) {
        int gI = n >> 5, h = n & 31;
        const float* wr = wih0 + gI * 65;
        float acc = wr[64] * __ldg(&wh2e[64 * 32 + h]);
#pragma unroll 4
        for (int e = 0; e < 64; ++e) acc += wr[e] * __ldg(&wh2e[e * 32 + h]);
        s_rnn[P_M + (gI >> 5) * PL_SM + (gI & 31) * 36 + h] = acc;
    }
    // fold bf[g] = bih0[g] + sum_e wih0[g][e]*bh2e[e] + wih0[g][64]*rf
    if (tid < 96) {
        const float* wr = wih0 + tid * 65;
        float acc = bih0[tid] + wr[64] * rf;
#pragma unroll 5
        for (int e = 0; e < 65; ++e) acc += wr[e] * __ldg(&bh2e[e]);
        s_rnn[P_BF + tid] = acc;
    }
    __syncthreads();

    const int g = tid >> 5;
    const int j = tid & 31;
    const int b0 = 4 * g;

    const float* hh0R = s_rnn + P_HH0, *hh0Z = hh0R + PL_SM, *hh0N = hh0Z + PL_SM;
    const float* ih1R = s_rnn + P_IH1, *ih1Z = ih1R + PL_SM, *ih1N = ih1Z + PL_SM;
    const float* hh1R = s_rnn + P_HH1, *hh1Z = hh1R + PL_SM, *hh1N = hh1Z + PL_SM;
    const float* ih2R = s_rnn + P_IH2, *ih2Z = ih2R + PL_SM, *ih2N = ih2Z + PL_SM;
    const float* hh2R = s_rnn + P_HH2, *hh2Z = hh2R + PL_SM, *hh2N = hh2Z + PL_SM;
    const float* MR   = s_rnn + P_M,   *MZ   = MR + PL_SM,   *MN   = MZ + PL_SM;

    float* stg   = s_rnn + P_STG + g * STG_WARP;
    float* st_h0 = stg;
    float* st_h1 = stg + 128;
    float* st_h2 = stg + 256;
    float* st_pv = stg + 384;

    const float brc0 = s_rnn[P_BF + j]      + bhh0[j];
    const float bzc0 = s_rnn[P_BF + 32 + j] + bhh0[32 + j];
    const float bin0 = s_rnn[P_BF + 64 + j];
    const float bhn0 = bhh0[64 + j];
    const float brc1 = bih1[j] + bhh1[j], bzc1 = bih1[32+j] + bhh1[32+j];
    const float bin1 = bih1[64+j],        bhn1 = bhh1[64+j];
    const float brc2 = bih2[j] + bhh2[j], bzc2 = bih2[32+j] + bhh2[32+j];
    const float bin2 = bih2[64+j],        bhn2 = bhh2[64+j];

    int* myflag = &g_progress[r * 4 + g];
    const int* waitflag = (r > 0) ? &g_progress[(r - 1) * 4 + g] : (const int*)0;
    int seen = 0;   // cached acquire value

    float h0[4] = {0,0,0,0}, h1[4] = {0,0,0,0}, h2[4] = {0,0,0,0};

    // ---- prologue: G values for t=0, x for t=1 ----
    float gc[12];
    int xvn[4];
    {
        int xv[4];
#pragma unroll
        for (int b = 0; b < 4; ++b) xv[b] = __ldg(&x[((b0 + b) * Rn + r) * Tn]);
#pragma unroll
        for (int b = 0; b < 4; ++b) {
            gc[b*3+0] = __ldg(&g_G[xv[b] * 96 + j]);
            gc[b*3+1] = __ldg(&g_G[xv[b] * 96 + 32 + j]);
            gc[b*3+2] = __ldg(&g_G[xv[b] * 96 + 64 + j]);
        }
        const int t1 = (Tn > 1) ? 1 : 0;
#pragma unroll
        for (int b = 0; b < 4; ++b) xvn[b] = __ldg(&x[((b0 + b) * Rn + r) * Tn + t1]);
    }

    for (int t = 0; t < Tn; ++t) {
        // 1. prefetch x[t+2] and G[x[t+1]]
        const int tnx = (t + 2 < Tn) ? t + 2 : Tn - 1;
        int xv2[4];
#pragma unroll
        for (int b = 0; b < 4; ++b) xv2[b] = __ldg(&x[((b0 + b) * Rn + r) * Tn + tnx]);
        float gn[12];
#pragma unroll
        for (int b = 0; b < 4; ++b) {
            gn[b*3+0] = __ldg(&g_G[xvn[b] * 96 + j]);
            gn[b*3+1] = __ldg(&g_G[xvn[b] * 96 + 32 + j]);
            gn[b*3+2] = __ldg(&g_G[xvn[b] * 96 + 64 + j]);
        }

        // 2. layer-0 recurrent dot (independent of previous row)
        unsigned long long ar[4]  = {0,0,0,0}, az[4]  = {0,0,0,0};
        unsigned long long ani[4] = {0,0,0,0}, anh[4] = {0,0,0,0};
        dotacc<8, 36, 32>(hh0R, hh0Z, hh0N, st_h0, j, ar, az, anh);

        // 3. previous-row coupling via folded M (32-dot)
        if (r > 0) {
            if (seen <= t) { do { seen = ld_acq(waitflag); } while (seen <= t); }
#pragma unroll
            for (int b = 0; b < 4; ++b)
                st_pv[b * 32 + j] = __ldcg(&g_out_h[(size_t)(((b0 + b) * Rn + (r - 1)) * Tn + t) * Hn + j]);
            __syncwarp();
            dotacc<8, 36, 32>(MR, MZ, MN, st_pv, j, ar, az, ani);
        }

        // 4. layer-0 activations (G-table term enters here)
#pragma unroll
        for (int b = 0; b < 4; ++b) {
            float gr = sigm(hsum(ar[b])  + gc[b*3+0] + brc0);
            float gz = sigm(hsum(az[b])  + gc[b*3+1] + bzc0);
            float gnv = tanh_f(hsum(ani[b]) + gc[b*3+2] + bin0 + gr * (hsum(anh[b]) + bhn0));
            h0[b] = gnv + gz * (h0[b] - gnv);
        }
        __syncwarp();
#pragma unroll
        for (int b = 0; b < 4; ++b) st_h0[b * 32 + j] = h0[b];
        __syncwarp();

        // 5. layers 1, 2
        gru_layer<8, 36, 32>(ih1R, ih1Z, ih1N, hh1R, hh1Z, hh1N,
                             st_h0, st_h1, j, brc1, bzc1, bin1, bhn1, h1);
        gru_layer<8, 36, 32>(ih2R, ih2Z, ih2N, hh2R, hh2Z, hh2N,
                             st_h1, st_h2, j, brc2, bzc2, bin2, bhn2, h2);

        // 6. publish + release
#pragma unroll
        for (int b = 0; b < 4; ++b)
            __stcg(&g_out_h[(size_t)(((b0 + b) * Rn + r) * Tn + t) * Hn + j], h2[b]);
        st_rel(myflag, t + 1);

        // rotate prefetch
#pragma unroll
        for (int k = 0; k < 12; ++k) gc[k] = gn[k];
#pragma unroll
        for (int b = 0; b < 4; ++b) xvn[b] = xv2[b];
    }
}

// ---------------------------------------------------------------------------
// Output projection v2: weights in registers, broadcast h reads.
// Block: 256 threads = 8 warps, 128 tokens. Warp w: pairs p=(w&3)*32+lane,
// tokens [(w>>2)*64, +64). Pair p covers vocab {2p, 2p+1}; tail pair 128
// (v=256,257) handled by threads 0..127.
#define PT 128

__global__ __launch_bounds__(256) void proj_kernel(
    const float* __restrict__ w_out,
    const float* __restrict__ b_out,
    float* __restrict__ pred)
{
    __shared__ float w_s[32 * 260];     // [h][v] padded
    __shared__ float h_s[PT * 36];      // [tok][h], stride 36 (16B-aligned)
    __shared__ float b_s[260];

    const int tid = threadIdx.x;

    if (blockIdx.x == 0) {
        for (int n = tid; n < Rn * 4; n += 256) g_progress[n] = 0;   // reset for next replay
    }

    for (int n = tid; n < VOCABn * 32; n += 256) {
        int v = n >> 5, h = n & 31;
        w_s[h * 260 + v] = w_out[n];
    }
    for (int n = tid; n < VOCABn; n += 256) b_s[n] = b_out[n];

    const size_t tok0 = (size_t)blockIdx.x * PT;
    const float* src = g_out_h + tok0 * 32;
    for (int n = tid; n < PT * 32; n += 256) {
        int i = n >> 5, h = n & 31;
        h_s[i * 36 + h] = src[n];
    }
    __syncthreads();

    const int warp = tid >> 5, lane = tid & 31;
    const int p = ((warp & 3) << 5) + lane;        // 0..127
    const int tokbase = (warp >> 2) * 64;

    // weights + bias into registers
    unsigned long long wreg[32];
#pragma unroll
    for (int h = 0; h < 32; ++h)
        wreg[h] = *(const unsigned long long*)&w_s[h * 260 + 2 * p];
    const unsigned long long b2 = *(const unsigned long long*)&b_s[2 * p];

#pragma unroll 1
    for (int tg = 0; tg < 16; ++tg) {
        const int tk = tokbase + tg * 4;
        unsigned long long a0 = b2, a1 = b2, a2 = b2, a3 = b2;
        const float* h0p = &h_s[(tk + 0) * 36];
        const float* h1p = &h_s[(tk + 1) * 36];
        const float* h2p = &h_s[(tk + 2) * 36];
        const float* h3p = &h_s[(tk + 3) * 36];
#pragma unroll
        for (int hq = 0; hq < 8; ++hq) {
            float4 q0 = *(const float4*)(h0p + hq * 4);
            float4 q1 = *(const float4*)(h1p + hq * 4);
            float4 q2 = *(const float4*)(h2p + hq * 4);
            float4 q3 = *(const float4*)(h3p + hq * 4);
            a0 = fma2(wreg[hq*4+0], dup2(q0.x), a0);
            a1 = fma2(wreg[hq*4+0], dup2(q1.x), a1);
            a2 = fma2(wreg[hq*4+0], dup2(q2.x), a2);
            a3 = fma2(wreg[hq*4+0], dup2(q3.x), a3);
            a0 = fma2(wreg[hq*4+1], dup2(q0.y), a0);
            a1 = fma2(wreg[hq*4+1], dup2(q1.y), a1);
            a2 = fma2(wreg[hq*4+1], dup2(q2.y), a2);
            a3 = fma2(wreg[hq*4+1], dup2(q3.y), a3);
            a0 = fma2(wreg[hq*4+2], dup2(q0.z), a0);
            a1 = fma2(wreg[hq*4+2], dup2(q1.z), a1);
            a2 = fma2(wreg[hq*4+2], dup2(q2.z), a2);
            a3 = fma2(wreg[hq*4+2], dup2(q3.z), a3);
            a0 = fma2(wreg[hq*4+3], dup2(q0.w), a0);
            a1 = fma2(wreg[hq*4+3], dup2(q1.w), a1);
            a2 = fma2(wreg[hq*4+3], dup2(q2.w), a2);
            a3 = fma2(wreg[hq*4+3], dup2(q3.w), a3);
        }
        float* outp = &pred[(tok0 + tk) * VOCABn + 2 * p];
        *(unsigned long long*)(outp + 0 * VOCABn) = a0;
        *(unsigned long long*)(outp + 1 * VOCABn) = a1;
        *(unsigned long long*)(outp + 2 * VOCABn) = a2;
        *(unsigned long long*)(outp + 3 * VOCABn) = a3;
    }

    // tail pair 128 (v = 256, 257)
    if (tid < PT) {
        unsigned long long acc = *(const unsigned long long*)&b_s[256];
        const float* hp = &h_s[tid * 36];
#pragma unroll
        for (int h = 0; h < 32; ++h)
            acc = fma2(*(const unsigned long long*)&w_s[h * 260 + 256], dup2(hp[h]), acc);
        *(unsigned long long*)&pred[(tok0 + tid) * VOCABn + 256] = acc;
    }
}

// ---------------------------------------------------------------------------

extern "C" void kernel_launch(void* const* d_in, const int* in_sizes, int n_in,
                              void* d_out, int out_size)
{
    const int*   x     = (const int*)  d_in[0];
    const float* emb   = (const float*)d_in[1];
    const float* wih0  = (const float*)d_in[2];
    const float* whh0  = (const float*)d_in[3];
    const float* bih0  = (const float*)d_in[4];
    const float* bhh0  = (const float*)d_in[5];
    const float* wih1  = (const float*)d_in[6];
    const float* whh1  = (const float*)d_in[7];
    const float* bih1  = (const float*)d_in[8];
    const float* bhh1  = (const float*)d_in[9];
    const float* wih2  = (const float*)d_in[10];
    const float* whh2  = (const float*)d_in[11];
    const float* bih2  = (const float*)d_in[12];
    const float* bhh2  = (const float*)d_in[13];
    const float* wh2e  = (const float*)d_in[14];
    const float* bh2e  = (const float*)d_in[15];
    const float* w_out = (const float*)d_in[16];
    const float* b_out = (const float*)d_in[17];
    float* pred = (float*)d_out;

    cudaFuncSetAttribute(rnn_kernel, cudaFuncAttributeMaxDynamicSharedMemorySize, SMEM_BYTES);

    prep_kernel<<<VOCABn, 96>>>(wih0, emb);
    rnn_kernel<<<Rn, 128, SMEM_BYTES>>>(x,
        wih0, whh0, bih0, bhh0,
        wih1, whh1, bih1, bhh1,
        wih2, whh2, bih2, bhh2,
        wh2e, bh2e);
    proj_kernel<<<NTOK / PT, 256>>>(w_out, b_out, pred);
}

// round 11
// speedup vs baseline: 2.2376x; 1.0682x over previous
#include <cuda_runtime.h>

// Problem constants
#define Bn     16
#define Rn     128
#define Tn     128
#define Hn     32
#define En     64
#define VOCABn 258
#define NTOK   (Bn*Rn*Tn)   // 262144

// Scratch
__device__ float g_out_h[(size_t)NTOK * Hn];
__device__ int   g_progress[Rn * 4];     // reset by proj_kernel for next replay
__device__ float g_G[VOCABn * 96];       // W_ih0[:, :64] @ embed_table[v]^T

// ---------------------------------------------------------------------------

__device__ __forceinline__ int ld_poll(const int* p) {
    int v;
    asm volatile("ld.global.cg.b32 %0, [%1];" : "=r"(v) : "l"(p));
    return v;
}
__device__ __forceinline__ void st_rel(int* p, int v) {
    asm volatile("st.global.release.gpu.b32 [%0], %1;" :: "l"(p), "r"(v) : "memory");
}
__device__ __forceinline__ float sigm(float x) {
    return __fdividef(1.0f, 1.0f + __expf(-x));
}
__device__ __forceinline__ float tanh_f(float x) {
    float e = __expf(2.0f * x);
    return 1.0f - __fdividef(2.0f, e + 1.0f);
}
__device__ __forceinline__ unsigned long long fma2(unsigned long long a, unsigned long long b,
                                                   unsigned long long c) {
    unsigned long long d;
    asm("fma.rn.f32x2 %0, %1, %2, %3;" : "=l"(d) : "l"(a), "l"(b), "l"(c));
    return d;
}
__device__ __forceinline__ float hsum(unsigned long long a) {
    float lo, hi;
    asm("mov.b64 {%0, %1}, %2;" : "=f"(lo), "=f"(hi) : "l"(a));
    return lo + hi;
}

// ---------------------------------------------------------------------------
// i-paired triple-plane dot (32-wide): acc{R,Z,N}[b] += sum_i w{p}[j][i]*in[b][i]
template<int G, int SW, int SI>
__device__ __forceinline__ void dotacc(
    const float* __restrict__ pR, const float* __restrict__ pZ, const float* __restrict__ pN,
    const float* __restrict__ in, int j,
    unsigned long long aR[4], unsigned long long aZ[4], unsigned long long aN[4])
{
    const float* wR = pR + j * SW;
    const float* wZ = pZ + j * SW;
    const float* wN = pN + j * SW;
#pragma unroll
    for (int g = 0; g < G; ++g) {
        const int i0 = g * 4;
        ulonglong2 w0 = *(const ulonglong2*)(wR + i0);
        ulonglong2 w1 = *(const ulonglong2*)(wZ + i0);
        ulonglong2 w2 = *(const ulonglong2*)(wN + i0);
        ulonglong2 v0 = *(const ulonglong2*)(in + 0 * SI + i0);
        ulonglong2 v1 = *(const ulonglong2*)(in + 1 * SI + i0);
        ulonglong2 v2 = *(const ulonglong2*)(in + 2 * SI + i0);
        ulonglong2 v3 = *(const ulonglong2*)(in + 3 * SI + i0);
        aR[0] = fma2(w0.x, v0.x, aR[0]); aZ[0] = fma2(w1.x, v0.x, aZ[0]); aN[0] = fma2(w2.x, v0.x, aN[0]);
        aR[1] = fma2(w0.x, v1.x, aR[1]); aZ[1] = fma2(w1.x, v1.x, aZ[1]); aN[1] = fma2(w2.x, v1.x, aN[1]);
        aR[2] = fma2(w0.x, v2.x, aR[2]); aZ[2] = fma2(w1.x, v2.x, aZ[2]); aN[2] = fma2(w2.x, v2.x, aN[2]);
        aR[3] = fma2(w0.x, v3.x, aR[3]); aZ[3] = fma2(w1.x, v3.x, aZ[3]); aN[3] = fma2(w2.x, v3.x, aN[3]);
        aR[0] = fma2(w0.y, v0.y, aR[0]); aZ[0] = fma2(w1.y, v0.y, aZ[0]); aN[0] = fma2(w2.y, v0.y, aN[0]);
        aR[1] = fma2(w0.y, v1.y, aR[1]); aZ[1] = fma2(w1.y, v1.y, aZ[1]); aN[1] = fma2(w2.y, v1.y, aN[1]);
        aR[2] = fma2(w0.y, v2.y, aR[2]); aZ[2] = fma2(w1.y, v2.y, aZ[2]); aN[2] = fma2(w2.y, v2.y, aN[2]);
        aR[3] = fma2(w0.y, v3.y, aR[3]); aZ[3] = fma2(w1.y, v3.y, aZ[3]); aN[3] = fma2(w2.y, v3.y, aN[3]);
    }
}

// ---------------------------------------------------------------------------
// prep: G[v][g] = sum_e wih0[g][e] * embed_table[v][e]
__global__ void prep_kernel(const float* __restrict__ wih0,
                            const float* __restrict__ emb)
{
    const int v = blockIdx.x;
    const int g = threadIdx.x;    // 96 threads
    const float* wr = wih0 + g * 65;
    const float* er = emb + v * En;
    float acc = 0.0f;
#pragma unroll 8
    for (int e = 0; e < En; ++e) acc += wr[e] * er[e];
    g_G[v * 96 + g] = acc;
}

// ---------------------------------------------------------------------------
// Smem layout (floats). Planes: R, Z, N per matrix, row stride 36.
#define PL_SM    1152                  // 32*36
#define P_HH0    0
#define P_IH1    (1*3456)
#define P_HH1    (2*3456)
#define P_IH2    (3*3456)
#define P_HH2    (4*3456)
#define P_M      (5*3456)              // folded W_ih0 @ W_h2e^T
#define P_STG    (6*3456)              // 20736
#define STG_WARP 512                   // h0/h1/h2/pv: 4*32 each
#define P_BF     (P_STG + 4*STG_WARP)  // folded layer-0 gate bias [96]
#define SM_FLOATS (P_BF + 128)
#define SMEM_BYTES (SM_FLOATS * 4)     // ~91.6 KB

extern __shared__ float s_rnn[];

__global__ __launch_bounds__(128, 1) void rnn_kernel(
    const int*   __restrict__ x,
    const float* __restrict__ wih0, const float* __restrict__ whh0,
    const float* __restrict__ bih0, const float* __restrict__ bhh0,
    const float* __restrict__ wih1, const float* __restrict__ whh1,
    const float* __restrict__ bih1, const float* __restrict__ bhh1,
    const float* __restrict__ wih2, const float* __restrict__ whh2,
    const float* __restrict__ bih2, const float* __restrict__ bhh2,
    const float* __restrict__ wh2e, const float* __restrict__ bh2e)
{
    const int r   = blockIdx.x;
    const int tid = threadIdx.x;
    const float rf = (float)r * (2.0f / 128.0f) - 1.0f;

    for (int n = tid; n < SM_FLOATS; n += 128) s_rnn[n] = 0.0f;
    __syncthreads();

    // stage recurrent weights into gate planes
    {
        const float* srcs[5] = { whh0, wih1, whh1, wih2, whh2 };
        const int    offs[5] = { P_HH0, P_IH1, P_HH1, P_IH2, P_HH2 };
#pragma unroll
        for (int m = 0; m < 5; ++m) {
            const float* src = srcs[m];
            float* dst = s_rnn + offs[m];
            for (int n = tid; n < 96 * 32; n += 128) {
                int gI = n >> 5, i = n & 31;
                dst[(gI >> 5) * PL_SM + (gI & 31) * 36 + i] = src[n];
            }
        }
    }
    // fold M[g][h] = sum_e wih0[g][e] * wh2e[e][h]
    for (int n = tid; n < 96 * 32; n += 128) {
        int gI = n >> 5, h = n & 31;
        const float* wr = wih0 + gI * 65;
        float acc = wr[64] * __ldg(&wh2e[64 * 32 + h]);
#pragma unroll 4
        for (int e = 0; e < 64; ++e) acc += wr[e] * __ldg(&wh2e[e * 32 + h]);
        s_rnn[P_M + (gI >> 5) * PL_SM + (gI & 31) * 36 + h] = acc;
    }
    // fold bf[g] = bih0[g] + sum_e wih0[g][e]*bh2e[e] + wih0[g][64]*rf
    if (tid < 96) {
        const float* wr = wih0 + tid * 65;
        float acc = bih0[tid] + wr[64] * rf;
#pragma unroll 5
        for (int e = 0; e < 65; ++e) acc += wr[e] * __ldg(&bh2e[e]);
        s_rnn[P_BF + tid] = acc;
    }
    __syncthreads();

    const int g = tid >> 5;
    const int j = tid & 31;
    const int b0 = 4 * g;

    const float* hh0R = s_rnn + P_HH0, *hh0Z = hh0R + PL_SM, *hh0N = hh0Z + PL_SM;
    const float* ih1R = s_rnn + P_IH1, *ih1Z = ih1R + PL_SM, *ih1N = ih1Z + PL_SM;
    const float* hh1R = s_rnn + P_HH1, *hh1Z = hh1R + PL_SM, *hh1N = hh1Z + PL_SM;
    const float* ih2R = s_rnn + P_IH2, *ih2Z = ih2R + PL_SM, *ih2N = ih2Z + PL_SM;
    const float* hh2R = s_rnn + P_HH2, *hh2Z = hh2R + PL_SM, *hh2N = hh2Z + PL_SM;
    const float* MR   = s_rnn + P_M,   *MZ   = MR + PL_SM,   *MN   = MZ + PL_SM;

    float* stg   = s_rnn + P_STG + g * STG_WARP;
    float* st_h0 = stg;
    float* st_h1 = stg + 128;
    float* st_h2 = stg + 256;
    float* st_pv = stg + 384;

    const float brc0 = s_rnn[P_BF + j]      + bhh0[j];
    const float bzc0 = s_rnn[P_BF + 32 + j] + bhh0[32 + j];
    const float bin0 = s_rnn[P_BF + 64 + j];
    const float bhn0 = bhh0[64 + j];
    const float brc1 = bih1[j] + bhh1[j], bzc1 = bih1[32+j] + bhh1[32+j];
    const float bin1 = bih1[64+j],        bhn1 = bhh1[64+j];
    const float brc2 = bih2[j] + bhh2[j], bzc2 = bih2[32+j] + bhh2[32+j];
    const float bin2 = bih2[64+j],        bhn2 = bhh2[64+j];

    int* myflag = &g_progress[r * 4 + g];
    const int* waitflag = (r > 0) ? &g_progress[(r - 1) * 4 + g] : (const int*)0;
    int seen = 0;

    float h0[4] = {0,0,0,0}, h1[4] = {0,0,0,0}, h2[4] = {0,0,0,0};

    // ---- prologue: G values for t=0, x for t=1 ----
    float gc[12];
    int xvn[4];
    {
        int xv[4];
#pragma unroll
        for (int b = 0; b < 4; ++b) xv[b] = __ldg(&x[((b0 + b) * Rn + r) * Tn]);
#pragma unroll
        for (int b = 0; b < 4; ++b) {
            gc[b*3+0] = __ldg(&g_G[xv[b] * 96 + j]);
            gc[b*3+1] = __ldg(&g_G[xv[b] * 96 + 32 + j]);
            gc[b*3+2] = __ldg(&g_G[xv[b] * 96 + 64 + j]);
        }
        const int t1 = (Tn > 1) ? 1 : 0;
#pragma unroll
        for (int b = 0; b < 4; ++b) xvn[b] = __ldg(&x[((b0 + b) * Rn + r) * Tn + t1]);
    }

    for (int t = 0; t < Tn; ++t) {
        // ---- PRE-WAIT phase: everything independent of the previous row ----
        const int tnx = (t + 2 < Tn) ? t + 2 : Tn - 1;
        int xv2[4];
#pragma unroll
        for (int b = 0; b < 4; ++b) xv2[b] = __ldg(&x[((b0 + b) * Rn + r) * Tn + tnx]);
        float gnx[12];
#pragma unroll
        for (int b = 0; b < 4; ++b) {
            gnx[b*3+0] = __ldg(&g_G[xvn[b] * 96 + j]);
            gnx[b*3+1] = __ldg(&g_G[xvn[b] * 96 + 32 + j]);
            gnx[b*3+2] = __ldg(&g_G[xvn[b] * 96 + 64 + j]);
        }

        // all three recurrent dots use h(t-1): off the inter-row chain
        unsigned long long ar0[4] = {0,0,0,0}, az0[4] = {0,0,0,0}, anh0[4] = {0,0,0,0};
        unsigned long long ar1[4] = {0,0,0,0}, az1[4] = {0,0,0,0}, anh1[4] = {0,0,0,0};
        unsigned long long ar2[4] = {0,0,0,0}, az2[4] = {0,0,0,0}, anh2[4] = {0,0,0,0};
        dotacc<8, 36, 32>(hh0R, hh0Z, hh0N, st_h0, j, ar0, az0, anh0);
        dotacc<8, 36, 32>(hh1R, hh1Z, hh1N, st_h1, j, ar1, az1, anh1);
        dotacc<8, 36, 32>(hh2R, hh2Z, hh2N, st_h2, j, ar2, az2, anh2);

        // ---- WAIT + previous-row coupling ----
        unsigned long long ani0[4] = {0,0,0,0};
        if (r > 0) {
            if (seen <= t) {
                seen = ld_poll(waitflag);
                while (seen <= t) { __nanosleep(40); seen = ld_poll(waitflag); }
                asm volatile("" ::: "memory");   // compile-time order: flag before pv
            }
            __syncwarp();
#pragma unroll
            for (int b = 0; b < 4; ++b)
                st_pv[b * 32 + j] = __ldcg(&g_out_h[(size_t)(((b0 + b) * Rn + (r - 1)) * Tn + t) * Hn + j]);
            __syncwarp();
            dotacc<8, 36, 32>(MR, MZ, MN, st_pv, j, ar0, az0, ani0);
        }

        // ---- layer-0 activations ----
#pragma unroll
        for (int b = 0; b < 4; ++b) {
            float gr = sigm(hsum(ar0[b]) + gc[b*3+0] + brc0);
            float gz = sigm(hsum(az0[b]) + gc[b*3+1] + bzc0);
            float gnv = tanh_f(hsum(ani0[b]) + gc[b*3+2] + bin0 + gr * (hsum(anh0[b]) + bhn0));
            h0[b] = gnv + gz * (h0[b] - gnv);
        }
        __syncwarp();
#pragma unroll
        for (int b = 0; b < 4; ++b) st_h0[b * 32 + j] = h0[b];
        __syncwarp();

        // ---- layer 1: only the ih dot is on the chain ----
        {
            unsigned long long ani[4] = {0,0,0,0};
            dotacc<8, 36, 32>(ih1R, ih1Z, ih1N, st_h0, j, ar1, az1, ani);
#pragma unroll
            for (int b = 0; b < 4; ++b) {
                float gr = sigm(hsum(ar1[b]) + brc1);
                float gz = sigm(hsum(az1[b]) + bzc1);
                float gnv = tanh_f(hsum(ani[b]) + bin1 + gr * (hsum(anh1[b]) + bhn1));
                h1[b] = gnv + gz * (h1[b] - gnv);
            }
            __syncwarp();
#pragma unroll
            for (int b = 0; b < 4; ++b) st_h1[b * 32 + j] = h1[b];
            __syncwarp();
        }

        // ---- layer 2 ----
        {
            unsigned long long ani[4] = {0,0,0,0};
            dotacc<8, 36, 32>(ih2R, ih2Z, ih2N, st_h1, j, ar2, az2, ani);
#pragma unroll
            for (int b = 0; b < 4; ++b) {
                float gr = sigm(hsum(ar2[b]) + brc2);
                float gz = sigm(hsum(az2[b]) + bzc2);
                float gnv = tanh_f(hsum(ani[b]) + bin2 + gr * (hsum(anh2[b]) + bhn2));
                h2[b] = gnv + gz * (h2[b] - gnv);
            }
            __syncwarp();
#pragma unroll
            for (int b = 0; b < 4; ++b) st_h2[b * 32 + j] = h2[b];
            __syncwarp();
        }

        // ---- publish + release ----
#pragma unroll
        for (int b = 0; b < 4; ++b)
            __stcg(&g_out_h[(size_t)(((b0 + b) * Rn + r) * Tn + t) * Hn + j], h2[b]);
        st_rel(myflag, t + 1);

        // rotate prefetch
#pragma unroll
        for (int k = 0; k < 12; ++k) gc[k] = gnx[k];
#pragma unroll
        for (int b = 0; b < 4; ++b) xvn[b] = xv2[b];
    }
}

// ---------------------------------------------------------------------------
// Output projection: weights in registers, pre-duplicated h pairs in dynamic smem.
#define PT 128
#define PROJ_DYN_BYTES (PT * 72 * 4)

extern __shared__ float h_s[];   // [PT][72]: h duplicated {h,h}, stride 72 floats

__global__ __launch_bounds__(256) void proj_kernel(
    const float* __restrict__ w_out,
    const float* __restrict__ b_out,
    float* __restrict__ pred)
{
    __shared__ float w_s[32 * 260];     // [h][v] padded
    __shared__ float b_s[260];

    const int tid = threadIdx.x;

    if (blockIdx.x == 0) {
        for (int n = tid; n < Rn * 4; n += 256) g_progress[n] = 0;   // reset for next replay
    }

    for (int n = tid; n < VOCABn * 32; n += 256) {
        int v = n >> 5, h = n & 31;
        w_s[h * 260 + v] = w_out[n];
    }
    for (int n = tid; n < VOCABn; n += 256) b_s[n] = b_out[n];

    const size_t tok0 = (size_t)blockIdx.x * PT;
    const float* src = g_out_h + tok0 * 32;
    for (int n = tid; n < PT * 32; n += 256) {
        int i = n >> 5, h = n & 31;
        float v = src[n];
        h_s[i * 72 + 2 * h]     = v;
        h_s[i * 72 + 2 * h + 1] = v;
    }
    __syncthreads();

    const int warp = tid >> 5, lane = tid & 31;
    const int p = ((warp & 3) << 5) + lane;        // 0..127
    const int tokbase = (warp >> 2) * 64;

    unsigned long long wreg[32];
#pragma unroll
    for (int h = 0; h < 32; ++h)
        wreg[h] = *(const unsigned long long*)&w_s[h * 260 + 2 * p];
    const unsigned long long b2 = *(const unsigned long long*)&b_s[2 * p];

#pragma unroll 1
    for (int tg = 0; tg < 16; ++tg) {
        const int tk = tokbase + tg * 4;
        unsigned long long a0 = b2, a1 = b2, a2 = b2, a3 = b2;
        const float* h0p = &h_s[(tk + 0) * 72];
        const float* h1p = &h_s[(tk + 1) * 72];
        const float* h2p = &h_s[(tk + 2) * 72];
        const float* h3p = &h_s[(tk + 3) * 72];
#pragma unroll
        for (int hq = 0; hq < 8; ++hq) {
            ulonglong2 qa0 = *(const ulonglong2*)(h0p + hq * 8);
            ulonglong2 qb0 = *(const ulonglong2*)(h0p + hq * 8 + 4);
            ulonglong2 qa1 = *(const ulonglong2*)(h1p + hq * 8);
            ulonglong2 qb1 = *(const ulonglong2*)(h1p + hq * 8 + 4);
            ulonglong2 qa2 = *(const ulonglong2*)(h2p + hq * 8);
            ulonglong2 qb2 = *(const ulonglong2*)(h2p + hq * 8 + 4);
            ulonglong2 qa3 = *(const ulonglong2*)(h3p + hq * 8);
            ulonglong2 qb3 = *(const ulonglong2*)(h3p + hq * 8 + 4);
            a0 = fma2(wreg[hq*4+0], qa0.x, a0);
            a1 = fma2(wreg[hq*4+0], qa1.x, a1);
            a2 = fma2(wreg[hq*4+0], qa2.x, a2);
            a3 = fma2(wreg[hq*4+0], qa3.x, a3);
            a0 = fma2(wreg[hq*4+1], qa0.y, a0);
            a1 = fma2(wreg[hq*4+1], qa1.y, a1);
            a2 = fma2(wreg[hq*4+1], qa2.y, a2);
            a3 = fma2(wreg[hq*4+1], qa3.y, a3);
            a0 = fma2(wreg[hq*4+2], qb0.x, a0);
            a1 = fma2(wreg[hq*4+2], qb1.x, a1);
            a2 = fma2(wreg[hq*4+2], qb2.x, a2);
            a3 = fma2(wreg[hq*4+2], qb3.x, a3);
            a0 = fma2(wreg[hq*4+3], qb0.y, a0);
            a1 = fma2(wreg[hq*4+3], qb1.y, a1);
            a2 = fma2(wreg[hq*4+3], qb2.y, a2);
            a3 = fma2(wreg[hq*4+3], qb3.y, a3);
        }
        float* outp = &pred[(tok0 + tk) * VOCABn + 2 * p];
        *(unsigned long long*)(outp + 0 * VOCABn) = a0;
        *(unsigned long long*)(outp + 1 * VOCABn) = a1;
        *(unsigned long long*)(outp + 2 * VOCABn) = a2;
        *(unsigned long long*)(outp + 3 * VOCABn) = a3;
    }

    // tail pair 128 (v = 256, 257)
    if (tid < PT) {
        unsigned long long acc = *(const unsigned long long*)&b_s[256];
        const float* hp = &h_s[tid * 72];
#pragma unroll
        for (int h = 0; h < 32; ++h)
            acc = fma2(*(const unsigned long long*)&w_s[h * 260 + 256],
                       *(const unsigned long long*)(hp + 2 * h), acc);
        *(unsigned long long*)&pred[(tok0 + tid) * VOCABn + 256] = acc;
    }
}

// ---------------------------------------------------------------------------

extern "C" void kernel_launch(void* const* d_in, const int* in_sizes, int n_in,
                              void* d_out, int out_size)
{
    const int*   x     = (const int*)  d_in[0];
    const float* emb   = (const float*)d_in[1];
    const float* wih0  = (const float*)d_in[2];
    const float* whh0  = (const float*)d_in[3];
    const float* bih0  = (const float*)d_in[4];
    const float* bhh0  = (const float*)d_in[5];
    const float* wih1  = (const float*)d_in[6];
    const float* whh1  = (const float*)d_in[7];
    const float* bih1  = (const float*)d_in[8];
    const float* bhh1  = (const float*)d_in[9];
    const float* wih2  = (const float*)d_in[10];
    const float* whh2  = (const float*)d_in[11];
    const float* bih2  = (const float*)d_in[12];
    const float* bhh2  = (const float*)d_in[13];
    const float* wh2e  = (const float*)d_in[14];
    const float* bh2e  = (const float*)d_in[15];
    const float* w_out = (const float*)d_in[16];
    const float* b_out = (const float*)d_in[17];
    float* pred = (float*)d_out;

    cudaFuncSetAttribute(rnn_kernel, cudaFuncAttributeMaxDynamicSharedMemorySize, SMEM_BYTES);
    cudaFuncSetAttribute(proj_kernel, cudaFuncAttributeMaxDynamicSharedMemorySize, PROJ_DYN_BYTES);

    prep_kernel<<<VOCABn, 96>>>(wih0, emb);
    rnn_kernel<<<Rn, 128, SMEM_BYTES>>>(x,
        wih0, whh0, bih0, bhh0,
        wih1, whh1, bih1, bhh1,
        wih2, whh2, bih2, bhh2,
        wh2e, bh2e);
    proj_kernel<<<NTOK / PT, 256, PROJ_DYN_BYTES>>>(w_out, b_out, pred);
}

// round 12
// speedup vs baseline: 2.3524x; 1.0513x over previous
#include <cuda_runtime.h>

// Problem constants
#define Bn     16
#define Rn     128
#define Tn     128
#define Hn     32
#define En     64
#define VOCABn 258
#define NTOK   (Bn*Rn*Tn)   // 262144

// Scratch
__device__ float g_out_h[(size_t)NTOK * Hn];
__device__ int   g_progress[Rn * 8];     // one flag per (row, 2-batch warp)
__device__ float g_G[VOCABn * 96];       // W_ih0[:, :64] @ embed_table[v]^T

// ---------------------------------------------------------------------------

__device__ __forceinline__ int ld_poll(const int* p) {
    int v;
    asm volatile("ld.global.cg.b32 %0, [%1];" : "=r"(v) : "l"(p));
    return v;
}
__device__ __forceinline__ void st_rel(int* p, int v) {
    asm volatile("st.global.release.gpu.b32 [%0], %1;" :: "l"(p), "r"(v) : "memory");
}
__device__ __forceinline__ float sigm(float x) {
    return __fdividef(1.0f, 1.0f + __expf(-x));
}
__device__ __forceinline__ float tanh_f(float x) {
    float e = __expf(2.0f * x);
    return 1.0f - __fdividef(2.0f, e + 1.0f);
}
__device__ __forceinline__ unsigned long long fma2(unsigned long long a, unsigned long long b,
                                                   unsigned long long c) {
    unsigned long long d;
    asm("fma.rn.f32x2 %0, %1, %2, %3;" : "=l"(d) : "l"(a), "l"(b), "l"(c));
    return d;
}
__device__ __forceinline__ float hsum(unsigned long long a) {
    float lo, hi;
    asm("mov.b64 {%0, %1}, %2;" : "=f"(lo), "=f"(hi) : "l"(a));
    return lo + hi;
}

// ---------------------------------------------------------------------------
// 2-batch i-paired triple-plane dot: acc{R,Z,N}[b] += sum_i w{p}[j][i]*in[b][i]
template<int G, int SW, int SI>
__device__ __forceinline__ void dotacc2(
    const float* __restrict__ pR, const float* __restrict__ pZ, const float* __restrict__ pN,
    const float* __restrict__ in, int j,
    unsigned long long aR[2], unsigned long long aZ[2], unsigned long long aN[2])
{
    const float* wR = pR + j * SW;
    const float* wZ = pZ + j * SW;
    const float* wN = pN + j * SW;
#pragma unroll
    for (int g = 0; g < G; ++g) {
        const int i0 = g * 4;
        ulonglong2 w0 = *(const ulonglong2*)(wR + i0);
        ulonglong2 w1 = *(const ulonglong2*)(wZ + i0);
        ulonglong2 w2 = *(const ulonglong2*)(wN + i0);
        ulonglong2 v0 = *(const ulonglong2*)(in + 0 * SI + i0);
        ulonglong2 v1 = *(const ulonglong2*)(in + 1 * SI + i0);
        aR[0] = fma2(w0.x, v0.x, aR[0]); aZ[0] = fma2(w1.x, v0.x, aZ[0]); aN[0] = fma2(w2.x, v0.x, aN[0]);
        aR[1] = fma2(w0.x, v1.x, aR[1]); aZ[1] = fma2(w1.x, v1.x, aZ[1]); aN[1] = fma2(w2.x, v1.x, aN[1]);
        aR[0] = fma2(w0.y, v0.y, aR[0]); aZ[0] = fma2(w1.y, v0.y, aZ[0]); aN[0] = fma2(w2.y, v0.y, aN[0]);
        aR[1] = fma2(w0.y, v1.y, aR[1]); aZ[1] = fma2(w1.y, v1.y, aZ[1]); aN[1] = fma2(w2.y, v1.y, aN[1]);
    }
}

// ---------------------------------------------------------------------------
// prep: G[v][g] = sum_e wih0[g][e] * embed_table[v][e]
__global__ void prep_kernel(const float* __restrict__ wih0,
                            const float* __restrict__ emb)
{
    const int v = blockIdx.x;
    const int g = threadIdx.x;    // 96 threads
    const float* wr = wih0 + g * 65;
    const float* er = emb + v * En;
    float acc = 0.0f;
#pragma unroll 8
    for (int e = 0; e < En; ++e) acc += wr[e] * er[e];
    g_G[v * 96 + g] = acc;
}

// ---------------------------------------------------------------------------
// Smem layout (floats). Planes: R, Z, N per matrix, row stride 36.
#define PL_SM    1152                  // 32*36
#define P_HH0    0
#define P_IH1    (1*3456)
#define P_HH1    (2*3456)
#define P_IH2    (3*3456)
#define P_HH2    (4*3456)
#define P_M      (5*3456)              // folded W_ih0 @ W_h2e^T
#define P_STG    (6*3456)              // 20736
#define STG_WARP 256                   // h0/h1/h2/pv: 2*32 each
#define P_BF     (P_STG + 8*STG_WARP)  // folded layer-0 gate bias [96]
#define SM_FLOATS (P_BF + 128)
#define SMEM_BYTES (SM_FLOATS * 4)     // ~91.6 KB

extern __shared__ float s_rnn[];

__global__ __launch_bounds__(256, 1) void rnn_kernel(
    const int*   __restrict__ x,
    const float* __restrict__ wih0, const float* __restrict__ whh0,
    const float* __restrict__ bih0, const float* __restrict__ bhh0,
    const float* __restrict__ wih1, const float* __restrict__ whh1,
    const float* __restrict__ bih1, const float* __restrict__ bhh1,
    const float* __restrict__ wih2, const float* __restrict__ whh2,
    const float* __restrict__ bih2, const float* __restrict__ bhh2,
    const float* __restrict__ wh2e, const float* __restrict__ bh2e)
{
    const int r   = blockIdx.x;
    const int tid = threadIdx.x;
    const float rf = (float)r * (2.0f / 128.0f) - 1.0f;

    for (int n = tid; n < SM_FLOATS; n += 256) s_rnn[n] = 0.0f;
    __syncthreads();

    // stage recurrent weights into gate planes
    {
        const float* srcs[5] = { whh0, wih1, whh1, wih2, whh2 };
        const int    offs[5] = { P_HH0, P_IH1, P_HH1, P_IH2, P_HH2 };
#pragma unroll
        for (int m = 0; m < 5; ++m) {
            const float* src = srcs[m];
            float* dst = s_rnn + offs[m];
            for (int n = tid; n < 96 * 32; n += 256) {
                int gI = n >> 5, i = n & 31;
                dst[(gI >> 5) * PL_SM + (gI & 31) * 36 + i] = src[n];
            }
        }
    }
    // fold M[g][h] = sum_e wih0[g][e] * wh2e[e][h]
    for (int n = tid; n < 96 * 32; n += 256) {
        int gI = n >> 5, h = n & 31;
        const float* wr = wih0 + gI * 65;
        float acc = wr[64] * __ldg(&wh2e[64 * 32 + h]);
#pragma unroll 4
        for (int e = 0; e < 64; ++e) acc += wr[e] * __ldg(&wh2e[e * 32 + h]);
        s_rnn[P_M + (gI >> 5) * PL_SM + (gI & 31) * 36 + h] = acc;
    }
    // fold bf[g] = bih0[g] + sum_e wih0[g][e]*bh2e[e] + wih0[g][64]*rf
    if (tid < 96) {
        const float* wr = wih0 + tid * 65;
        float acc = bih0[tid] + wr[64] * rf;
#pragma unroll 5
        for (int e = 0; e < 65; ++e) acc += wr[e] * __ldg(&bh2e[e]);
        s_rnn[P_BF + tid] = acc;
    }
    __syncthreads();

    const int g = tid >> 5;   // warp id 0..7, handles batches 2g, 2g+1
    const int j = tid & 31;
    const int b0 = 2 * g;

    const float* hh0R = s_rnn + P_HH0, *hh0Z = hh0R + PL_SM, *hh0N = hh0Z + PL_SM;
    const float* ih1R = s_rnn + P_IH1, *ih1Z = ih1R + PL_SM, *ih1N = ih1Z + PL_SM;
    const float* hh1R = s_rnn + P_HH1, *hh1Z = hh1R + PL_SM, *hh1N = hh1Z + PL_SM;
    const float* ih2R = s_rnn + P_IH2, *ih2Z = ih2R + PL_SM, *ih2N = ih2Z + PL_SM;
    const float* hh2R = s_rnn + P_HH2, *hh2Z = hh2R + PL_SM, *hh2N = hh2Z + PL_SM;
    const float* MR   = s_rnn + P_M,   *MZ   = MR + PL_SM,   *MN   = MZ + PL_SM;

    float* stg   = s_rnn + P_STG + g * STG_WARP;
    float* st_h0 = stg;            // [b*32 + j], b in {0,1}
    float* st_h1 = stg + 64;
    float* st_h2 = stg + 128;
    float* st_pv = stg + 192;

    const float brc0 = s_rnn[P_BF + j]      + bhh0[j];
    const float bzc0 = s_rnn[P_BF + 32 + j] + bhh0[32 + j];
    const float bin0 = s_rnn[P_BF + 64 + j];
    const float bhn0 = bhh0[64 + j];
    const float brc1 = bih1[j] + bhh1[j], bzc1 = bih1[32+j] + bhh1[32+j];
    const float bin1 = bih1[64+j],        bhn1 = bhh1[64+j];
    const float brc2 = bih2[j] + bhh2[j], bzc2 = bih2[32+j] + bhh2[32+j];
    const float bin2 = bih2[64+j],        bhn2 = bhh2[64+j];

    int* myflag = &g_progress[r * 8 + g];
    const int* waitflag = (r > 0) ? &g_progress[(r - 1) * 8 + g] : (const int*)0;
    int seen = 0;

    float h0[2] = {0,0}, h1[2] = {0,0}, h2[2] = {0,0};

    // ---- prologue: G values for t=0, x for t=1 ----
    float gc[6];
    int xvn[2];
    {
        int xv[2];
#pragma unroll
        for (int b = 0; b < 2; ++b) xv[b] = __ldg(&x[((b0 + b) * Rn + r) * Tn]);
#pragma unroll
        for (int b = 0; b < 2; ++b) {
            gc[b*3+0] = __ldg(&g_G[xv[b] * 96 + j]);
            gc[b*3+1] = __ldg(&g_G[xv[b] * 96 + 32 + j]);
            gc[b*3+2] = __ldg(&g_G[xv[b] * 96 + 64 + j]);
        }
        const int t1 = (Tn > 1) ? 1 : 0;
#pragma unroll
        for (int b = 0; b < 2; ++b) xvn[b] = __ldg(&x[((b0 + b) * Rn + r) * Tn + t1]);
    }

    for (int t = 0; t < Tn; ++t) {
        // ---- PRE-WAIT: prefetch + all recurrent (h(t-1)) dots ----
        const int tnx = (t + 2 < Tn) ? t + 2 : Tn - 1;
        int xv2[2];
#pragma unroll
        for (int b = 0; b < 2; ++b) xv2[b] = __ldg(&x[((b0 + b) * Rn + r) * Tn + tnx]);
        float gnx[6];
#pragma unroll
        for (int b = 0; b < 2; ++b) {
            gnx[b*3+0] = __ldg(&g_G[xvn[b] * 96 + j]);
            gnx[b*3+1] = __ldg(&g_G[xvn[b] * 96 + 32 + j]);
            gnx[b*3+2] = __ldg(&g_G[xvn[b] * 96 + 64 + j]);
        }

        unsigned long long ar0[2] = {0,0}, az0[2] = {0,0}, anh0[2] = {0,0};
        unsigned long long ar1[2] = {0,0}, az1[2] = {0,0}, anh1[2] = {0,0};
        unsigned long long ar2[2] = {0,0}, az2[2] = {0,0}, anh2[2] = {0,0};
        dotacc2<8, 36, 32>(hh0R, hh0Z, hh0N, st_h0, j, ar0, az0, anh0);
        dotacc2<8, 36, 32>(hh1R, hh1Z, hh1N, st_h1, j, ar1, az1, anh1);
        dotacc2<8, 36, 32>(hh2R, hh2Z, hh2N, st_h2, j, ar2, az2, anh2);

        // ---- WAIT + previous-row coupling ----
        unsigned long long ani0[2] = {0,0};
        if (r > 0) {
            if (seen <= t) {
                seen = ld_poll(waitflag);
                while (seen <= t) { __nanosleep(20); seen = ld_poll(waitflag); }
                asm volatile("" ::: "memory");
            }
            __syncwarp();
#pragma unroll
            for (int b = 0; b < 2; ++b)
                st_pv[b * 32 + j] = __ldcg(&g_out_h[(size_t)(((b0 + b) * Rn + (r - 1)) * Tn + t) * Hn + j]);
            __syncwarp();
            dotacc2<8, 36, 32>(MR, MZ, MN, st_pv, j, ar0, az0, ani0);
        }

        // ---- layer-0 activations ----
#pragma unroll
        for (int b = 0; b < 2; ++b) {
            float gr = sigm(hsum(ar0[b]) + gc[b*3+0] + brc0);
            float gz = sigm(hsum(az0[b]) + gc[b*3+1] + bzc0);
            float gnv = tanh_f(hsum(ani0[b]) + gc[b*3+2] + bin0 + gr * (hsum(anh0[b]) + bhn0));
            h0[b] = gnv + gz * (h0[b] - gnv);
        }
        __syncwarp();
#pragma unroll
        for (int b = 0; b < 2; ++b) st_h0[b * 32 + j] = h0[b];
        __syncwarp();

        // ---- layer 1 ----
        {
            unsigned long long ani[2] = {0,0};
            dotacc2<8, 36, 32>(ih1R, ih1Z, ih1N, st_h0, j, ar1, az1, ani);
#pragma unroll
            for (int b = 0; b < 2; ++b) {
                float gr = sigm(hsum(ar1[b]) + brc1);
                float gz = sigm(hsum(az1[b]) + bzc1);
                float gnv = tanh_f(hsum(ani[b]) + bin1 + gr * (hsum(anh1[b]) + bhn1));
                h1[b] = gnv + gz * (h1[b] - gnv);
            }
            __syncwarp();
#pragma unroll
            for (int b = 0; b < 2; ++b) st_h1[b * 32 + j] = h1[b];
            __syncwarp();
        }

        // ---- layer 2 ----
        {
            unsigned long long ani[2] = {0,0};
            dotacc2<8, 36, 32>(ih2R, ih2Z, ih2N, st_h1, j, ar2, az2, ani);
#pragma unroll
            for (int b = 0; b < 2; ++b) {
                float gr = sigm(hsum(ar2[b]) + brc2);
                float gz = sigm(hsum(az2[b]) + bzc2);
                float gnv = tanh_f(hsum(ani[b]) + bin2 + gr * (hsum(anh2[b]) + bhn2));
                h2[b] = gnv + gz * (h2[b] - gnv);
            }
            __syncwarp();
#pragma unroll
            for (int b = 0; b < 2; ++b) st_h2[b * 32 + j] = h2[b];
            __syncwarp();
        }

        // ---- publish + release ----
#pragma unroll
        for (int b = 0; b < 2; ++b)
            __stcg(&g_out_h[(size_t)(((b0 + b) * Rn + r) * Tn + t) * Hn + j], h2[b]);
        st_rel(myflag, t + 1);

        // rotate prefetch
#pragma unroll
        for (int k = 0; k < 6; ++k) gc[k] = gnx[k];
#pragma unroll
        for (int b = 0; b < 2; ++b) xvn[b] = xv2[b];
    }
}

// ---------------------------------------------------------------------------
// Output projection: weights in registers, pre-duplicated h pairs in dynamic smem.
#define PT 128
#define PROJ_DYN_BYTES (PT * 72 * 4)

extern __shared__ float h_s[];   // [PT][72]: h duplicated {h,h}, stride 72 floats

__global__ __launch_bounds__(256) void proj_kernel(
    const float* __restrict__ w_out,
    const float* __restrict__ b_out,
    float* __restrict__ pred)
{
    __shared__ float w_s[32 * 260];     // [h][v] padded
    __shared__ float b_s[260];

    const int tid = threadIdx.x;

    if (blockIdx.x == 0) {
        for (int n = tid; n < Rn * 8; n += 256) g_progress[n] = 0;   // reset for next replay
    }

    for (int n = tid; n < VOCABn * 32; n += 256) {
        int v = n >> 5, h = n & 31;
        w_s[h * 260 + v] = w_out[n];
    }
    for (int n = tid; n < VOCABn; n += 256) b_s[n] = b_out[n];

    const size_t tok0 = (size_t)blockIdx.x * PT;
    const float* src = g_out_h + tok0 * 32;
    for (int n = tid; n < PT * 32; n += 256) {
        int i = n >> 5, h = n & 31;
        float v = src[n];
        h_s[i * 72 + 2 * h]     = v;
        h_s[i * 72 + 2 * h + 1] = v;
    }
    __syncthreads();

    const int warp = tid >> 5, lane = tid & 31;
    const int p = ((warp & 3) << 5) + lane;        // 0..127
    const int tokbase = (warp >> 2) * 64;

    unsigned long long wreg[32];
#pragma unroll
    for (int h = 0; h < 32; ++h)
        wreg[h] = *(const unsigned long long*)&w_s[h * 260 + 2 * p];
    const unsigned long long b2 = *(const unsigned long long*)&b_s[2 * p];

#pragma unroll 1
    for (int tg = 0; tg < 16; ++tg) {
        const int tk = tokbase + tg * 4;
        unsigned long long a0 = b2, a1 = b2, a2 = b2, a3 = b2;
        const float* h0p = &h_s[(tk + 0) * 72];
        const float* h1p = &h_s[(tk + 1) * 72];
        const float* h2p = &h_s[(tk + 2) * 72];
        const float* h3p = &h_s[(tk + 3) * 72];
#pragma unroll
        for (int hq = 0; hq < 8; ++hq) {
            ulonglong2 qa0 = *(const ulonglong2*)(h0p + hq * 8);
            ulonglong2 qb0 = *(const ulonglong2*)(h0p + hq * 8 + 4);
            ulonglong2 qa1 = *(const ulonglong2*)(h1p + hq * 8);
            ulonglong2 qb1 = *(const ulonglong2*)(h1p + hq * 8 + 4);
            ulonglong2 qa2 = *(const ulonglong2*)(h2p + hq * 8);
            ulonglong2 qb2 = *(const ulonglong2*)(h2p + hq * 8 + 4);
            ulonglong2 qa3 = *(const ulonglong2*)(h3p + hq * 8);
            ulonglong2 qb3 = *(const ulonglong2*)(h3p + hq * 8 + 4);
            a0 = fma2(wreg[hq*4+0], qa0.x, a0);
            a1 = fma2(wreg[hq*4+0], qa1.x, a1);
            a2 = fma2(wreg[hq*4+0], qa2.x, a2);
            a3 = fma2(wreg[hq*4+0], qa3.x, a3);
            a0 = fma2(wreg[hq*4+1], qa0.y, a0);
            a1 = fma2(wreg[hq*4+1], qa1.y, a1);
            a2 = fma2(wreg[hq*4+1], qa2.y, a2);
            a3 = fma2(wreg[hq*4+1], qa3.y, a3);
            a0 = fma2(wreg[hq*4+2], qb0.x, a0);
            a1 = fma2(wreg[hq*4+2], qb1.x, a1);
            a2 = fma2(wreg[hq*4+2], qb2.x, a2);
            a3 = fma2(wreg[hq*4+2], qb3.x, a3);
            a0 = fma2(wreg[hq*4+3], qb0.y, a0);
            a1 = fma2(wreg[hq*4+3], qb1.y, a1);
            a2 = fma2(wreg[hq*4+3], qb2.y, a2);
            a3 = fma2(wreg[hq*4+3], qb3.y, a3);
        }
        float* outp = &pred[(tok0 + tk) * VOCABn + 2 * p];
        *(unsigned long long*)(outp + 0 * VOCABn) = a0;
        *(unsigned long long*)(outp + 1 * VOCABn) = a1;
        *(unsigned long long*)(outp + 2 * VOCABn) = a2;
        *(unsigned long long*)(outp + 3 * VOCABn) = a3;
    }

    // tail pair 128 (v = 256, 257)
    if (tid < PT) {
        unsigned long long acc = *(const unsigned long long*)&b_s[256];
        const float* hp = &h_s[tid * 72];
#pragma unroll
        for (int h = 0; h < 32; ++h)
            acc = fma2(*(const unsigned long long*)&w_s[h * 260 + 256],
                       *(const unsigned long long*)(hp + 2 * h), acc);
        *(unsigned long long*)&pred[(tok0 + tid) * VOCABn + 256] = acc;
    }
}

// ---------------------------------------------------------------------------

extern "C" void kernel_launch(void* const* d_in, const int* in_sizes, int n_in,
                              void* d_out, int out_size)
{
    const int*   x     = (const int*)  d_in[0];
    const float* emb   = (const float*)d_in[1];
    const float* wih0  = (const float*)d_in[2];
    const float* whh0  = (const float*)d_in[3];
    const float* bih0  = (const float*)d_in[4];
    const float* bhh0  = (const float*)d_in[5];
    const float* wih1  = (const float*)d_in[6];
    const float* whh1  = (const float*)d_in[7];
    const float* bih1  = (const float*)d_in[8];
    const float* bhh1  = (const float*)d_in[9];
    const float* wih2  = (const float*)d_in[10];
    const float* whh2  = (const float*)d_in[11];
    const float* bih2  = (const float*)d_in[12];
    const float* bhh2  = (const float*)d_in[13];
    const float* wh2e  = (const float*)d_in[14];
    const float* bh2e  = (const float*)d_in[15];
    const float* w_out = (const float*)d_in[16];
    const float* b_out = (const float*)d_in[17];
    float* pred = (float*)d_out;

    cudaFuncSetAttribute(rnn_kernel, cudaFuncAttributeMaxDynamicSharedMemorySize, SMEM_BYTES);
    cudaFuncSetAttribute(proj_kernel, cudaFuncAttributeMaxDynamicSharedMemorySize, PROJ_DYN_BYTES);

    prep_kernel<<<VOCABn, 96>>>(wih0, emb);
    rnn_kernel<<<Rn, 256, SMEM_BYTES>>>(x,
        wih0, whh0, bih0, bhh0,
        wih1, whh1, bih1, bhh1,
        wih2, whh2, bih2, bhh2,
        wh2e, bh2e);
    proj_kernel<<<NTOK / PT, 256, PROJ_DYN_BYTES>>>(w_out, b_out, pred);
}